// round 4
// baseline (speedup 1.0000x reference)
#include <cuda_runtime.h>
#include <cuda_bf16.h>
#include <math.h>
#include <stdint.h>

// ---------------- problem constants ----------------
#define BB 4
#define NN 2048
#define KK 20
#define PTS (BB*NN)          // 8192
#define SLOPE 0.2f
#define EPS_BN 1e-5f

// ---------------- device scratch (no allocs allowed) ----------------
__device__ float g_F0[PTS*3];
__device__ float g_F1[PTS*64];
__device__ float g_F2[PTS*64];
__device__ float g_F3[PTS*128];
__device__ float g_F4[PTS*256];
__device__ float g_negd[(size_t)NN*NN];      // 16.8MB: ONE batch slice, reused (L2-resident)
__device__ int   g_idx[PTS*KK];
__device__ float g_Y[PTS*512];               // transform out, max 2*O = 512
__device__ float g_Wcat[512*128];            // max (2O=512) x (C=128)
__device__ float g_sq[PTS];

__device__ __forceinline__ unsigned ordkey(float f) {
    unsigned u = __float_as_uint(f);
    return (u & 0x80000000u) ? ~u : (u | 0x80000000u);
}

// ---------------- transpose (B,3,N) -> (B,N,3) ----------------
__global__ void transpose_in(const float* __restrict__ x, float* __restrict__ F0) {
    int t = blockIdx.x*blockDim.x + threadIdx.x;
    if (t >= BB*3*NN) return;
    int b = t / (3*NN);
    int rem = t % (3*NN);
    int c = rem / NN, n = rem % NN;
    F0[(size_t)(b*NN + n)*3 + c] = x[t];
}

// ---------------- squared norms per point ----------------
__global__ void sqnorm_kernel(const float* __restrict__ F, float* __restrict__ sq, int C) {
    int p = blockIdx.x*blockDim.x + threadIdx.x;
    if (p >= PTS) return;
    const float* f = F + (size_t)p*C;
    float s = 0.f;
    for (int c = 0; c < C; ++c) s = fmaf(f[c], f[c], s);
    sq[p] = s;
}

// =====================================================================
// 128x128 tile SGEMM (NT), 256 threads, 8x8 microtile, reg-prefetch.
// MODE 0: Cmat[i][j] = sum_k A[i,k]*Bt[j,k]
// MODE 1: distance epilogue v = 2*acc - sq[i] - sq[j]; upper-triangle grid
//         (bx>=by) with mirrored transposed store for off-diagonal tiles.
// MODE 2: fused final layer: y = s*acc + b, lrelu, column-max over the
//         128 rows of the tile, atomicMax(ordkey) into outu (per batch).
// =====================================================================
template<int MODE>
__global__ __launch_bounds__(256)
void gemm128(const float* __restrict__ A, const float* __restrict__ Bt,
             float* __restrict__ Cmat, int Nc, int K,
             const float* __restrict__ sq,
             const float* __restrict__ gam, const float* __restrict__ bet,
             unsigned* __restrict__ outu)
{
    int bx = blockIdx.x, by = blockIdx.y;
    if (MODE == 1 && bx < by) return;     // triangle only

    __shared__ __align__(16) float sbuf[4352];   // As[16][136] + Bs[16][136]
    float* As = sbuf;
    float* Bs = sbuf + 2176;

    int tid = threadIdx.x;
    int tx = tid & 15, ty = tid >> 4;
    int i0 = by * 128, j0 = bx * 128;

    float acc[8][8];
    #pragma unroll
    for (int i = 0; i < 8; ++i)
        #pragma unroll
        for (int j = 0; j < 8; ++j) acc[i][j] = 0.f;

    float ra[8], rb[8];

    auto loadG = [&](int kt) {
        int k0 = kt * 16;
        #pragma unroll
        for (int u = 0; u < 8; ++u) {
            int l = tid + 256*u;
            int r = l >> 4, kk = l & 15;
            bool ok = (k0 + kk) < K;
            ra[u] = ok ? A [(size_t)(i0 + r)*K + k0 + kk] : 0.f;
            rb[u] = ok ? Bt[(size_t)(j0 + r)*K + k0 + kk] : 0.f;
        }
    };
    auto storeS = [&]() {
        #pragma unroll
        for (int u = 0; u < 8; ++u) {
            int l = tid + 256*u;
            int r = l >> 4, kk = l & 15;
            As[kk*136 + r] = ra[u];
            Bs[kk*136 + r] = rb[u];
        }
    };

    int KT = (K + 15) >> 4;
    loadG(0);
    for (int kt = 0; kt < KT; ++kt) {
        __syncthreads();
        storeS();
        __syncthreads();
        if (kt + 1 < KT) loadG(kt + 1);
        #pragma unroll
        for (int k = 0; k < 16; ++k) {
            float4 a0 = *(const float4*)&As[k*136 + ty*8];
            float4 a1 = *(const float4*)&As[k*136 + ty*8 + 4];
            float4 b0 = *(const float4*)&Bs[k*136 + tx*8];
            float4 b1 = *(const float4*)&Bs[k*136 + tx*8 + 4];
            float av[8] = {a0.x,a0.y,a0.z,a0.w,a1.x,a1.y,a1.z,a1.w};
            float bv[8] = {b0.x,b0.y,b0.z,b0.w,b1.x,b1.y,b1.z,b1.w};
            #pragma unroll
            for (int ii = 0; ii < 8; ++ii)
                #pragma unroll
                for (int jj = 0; jj < 8; ++jj)
                    acc[ii][jj] = fmaf(av[ii], bv[jj], acc[ii][jj]);
        }
    }

    if (MODE == 0) {
        #pragma unroll
        for (int ii = 0; ii < 8; ++ii) {
            size_t base = (size_t)(i0 + ty*8 + ii)*Nc + j0 + tx*8;
            float4 v0 = make_float4(acc[ii][0], acc[ii][1], acc[ii][2], acc[ii][3]);
            float4 v1 = make_float4(acc[ii][4], acc[ii][5], acc[ii][6], acc[ii][7]);
            *(float4*)&Cmat[base]     = v0;
            *(float4*)&Cmat[base + 4] = v1;
        }
    }
    else if (MODE == 1) {
        float sqi[8], sqj[8];
        #pragma unroll
        for (int ii = 0; ii < 8; ++ii) sqi[ii] = sq[i0 + ty*8 + ii];
        #pragma unroll
        for (int jj = 0; jj < 8; ++jj) sqj[jj] = sq[j0 + tx*8 + jj];
        #pragma unroll
        for (int ii = 0; ii < 8; ++ii)
            #pragma unroll
            for (int jj = 0; jj < 8; ++jj)
                acc[ii][jj] = 2.0f*acc[ii][jj] - sqi[ii] - sqj[jj];

        #pragma unroll
        for (int ii = 0; ii < 8; ++ii) {
            size_t base = (size_t)(i0 + ty*8 + ii)*Nc + j0 + tx*8;
            float4 v0 = make_float4(acc[ii][0], acc[ii][1], acc[ii][2], acc[ii][3]);
            float4 v1 = make_float4(acc[ii][4], acc[ii][5], acc[ii][6], acc[ii][7]);
            *(float4*)&Cmat[base]     = v0;
            *(float4*)&Cmat[base + 4] = v1;
        }
        if (bx != by) {
            // mirror: Cmat[j][i] = v[i][j], staged through smem (reuse sbuf)
            for (int c = 0; c < 4; ++c) {
                __syncthreads();
                if ((tx >> 2) == c) {
                    #pragma unroll
                    for (int jj = 0; jj < 8; ++jj)
                        #pragma unroll
                        for (int ii = 0; ii < 8; ++ii)
                            sbuf[((tx & 3)*8 + jj)*136 + ty*8 + ii] = acc[ii][jj];
                }
                __syncthreads();
                int s2 = tid >> 3;           // 0..31
                int cs = (tid & 7) * 16;     // 0..112
                size_t base = (size_t)(j0 + 32*c + s2)*Nc + i0 + cs;
                #pragma unroll
                for (int w = 0; w < 4; ++w)
                    *(float4*)&Cmat[base + 4*w] =
                        *(const float4*)&sbuf[s2*136 + cs + 4*w];
            }
        }
    }
    else { // MODE == 2: fused affine+lrelu+colmax, N fixed 1024
        int b = i0 >> 11;
        float colmax[8];
        #pragma unroll
        for (int jj = 0; jj < 8; ++jj) {
            int col = j0 + tx*8 + jj;
            float sc = gam[col] / sqrtf(1.0f + EPS_BN);
            float bb = bet[col];
            float m = -INFINITY;
            #pragma unroll
            for (int ii = 0; ii < 8; ++ii) {
                float y = fmaf(sc, acc[ii][jj], bb);
                y = (y >= 0.f) ? y : SLOPE*y;
                m = fmaxf(m, y);
            }
            colmax[jj] = m;
        }
        __syncthreads();
        #pragma unroll
        for (int jj = 0; jj < 8; ++jj)
            sbuf[ty*136 + tx*8 + jj] = colmax[jj];
        __syncthreads();
        if (tid < 128) {
            float m = -INFINITY;
            #pragma unroll
            for (int t2 = 0; t2 < 16; ++t2)
                m = fmaxf(m, sbuf[t2*136 + tid]);
            atomicMax(&outu[b*1024 + j0 + tid], ordkey(m));
        }
    }
}

// ---------------- radix/bin-select top-20 per row (per-batch) ----------
__global__ __launch_bounds__(256)
void topk_radix(const float* __restrict__ negd, int* __restrict__ idx_out)
{
    int row = blockIdx.x;                        // local n within batch
    const float* d = negd + (size_t)row * NN;

    __shared__ unsigned int hist[2048];
    __shared__ unsigned long long cand[2048];
    __shared__ unsigned int warp_suf[8];
    __shared__ int s_B, s_above, s_nout, s_ncand;
    __shared__ unsigned long long s_best;

    int t = threadIdx.x;

    #pragma unroll
    for (int u = 0; u < 8; ++u) hist[t + 256*u] = 0;
    if (t == 0) { s_nout = 0; s_ncand = 0; }
    __syncthreads();

    unsigned int ukey[8];
    #pragma unroll
    for (int u = 0; u < 8; ++u) {
        int j = t + 256*u;
        unsigned int ub = __float_as_uint(d[j]);
        ub = (ub & 0x80000000u) ? ~ub : (ub | 0x80000000u);
        ukey[u] = ub;
        atomicAdd(&hist[ub >> 21], 1u);
    }
    __syncthreads();

    unsigned int local = 0;
    #pragma unroll
    for (int u = 0; u < 8; ++u) local += hist[8*t + u];

    unsigned int lane = t & 31, wid = t >> 5;
    unsigned int x = local;
    #pragma unroll
    for (int o = 1; o < 32; o <<= 1) {
        unsigned int y = __shfl_down_sync(0xffffffffu, x, o);
        if (lane + o < 32) x += y;
    }
    unsigned int warp_total = __shfl_sync(0xffffffffu, x, 0);
    if (lane == 0) warp_suf[wid] = warp_total;
    __syncthreads();
    unsigned int above_warp = 0;
    for (int w = wid + 1; w < 8; ++w) above_warp += warp_suf[w];
    unsigned int suffix_above = above_warp + (x - local);

    unsigned int cum = suffix_above;
    #pragma unroll
    for (int u = 7; u >= 0; --u) {
        unsigned int h = hist[8*t + u];
        if (cum < KK && cum + h >= KK) { s_B = 8*t + u; s_above = (int)cum; }
        cum += h;
    }
    __syncthreads();
    int B = s_B;
    int r = KK - s_above;

    #pragma unroll
    for (int u = 0; u < 8; ++u) {
        int j = t + 256*u;
        int bin = ukey[u] >> 21;
        if (bin > B) {
            int pos = atomicAdd(&s_nout, 1);
            idx_out[row*KK + pos] = j;
        } else if (bin == B) {
            int pos = atomicAdd(&s_ncand, 1);
            cand[pos] = ((unsigned long long)ukey[u] << 32) | (unsigned int)(~j);
        }
    }
    __syncthreads();
    int ncand = s_ncand;
    int base = s_nout;

    __shared__ unsigned long long wkey[8];
    for (int rr = 0; rr < r; ++rr) {
        unsigned long long best = 0ull;
        for (int j = t; j < ncand; j += 256) {
            unsigned long long k = cand[j];
            best = (k > best) ? k : best;
        }
        #pragma unroll
        for (int o = 16; o; o >>= 1) {
            unsigned long long other = __shfl_xor_sync(0xffffffffu, best, o);
            best = (other > best) ? other : best;
        }
        if ((t & 31) == 0) wkey[t >> 5] = best;
        __syncthreads();
        if (t == 0) {
            unsigned long long b2 = wkey[0];
            #pragma unroll
            for (int w = 1; w < 8; ++w) b2 = (wkey[w] > b2) ? wkey[w] : b2;
            s_best = b2;
            idx_out[row*KK + base + rr] =
                (int)(~(unsigned int)(b2 & 0xffffffffull));
        }
        __syncthreads();
        unsigned long long bb = s_best;
        for (int j = t; j < ncand; j += 256)
            if (cand[j] == bb) cand[j] = 0ull;
        __syncthreads();
    }
}

// ---------------- build Wcat = [W_left ; W_right - W_left] ----------------
__global__ void prep_wcat(const float* __restrict__ W, float* __restrict__ Wcat,
                          int O, int C)
{
    int t = blockIdx.x*blockDim.x + threadIdx.x;
    if (t >= 2*O*C) return;
    int j = t / C, c = t % C;
    float v;
    if (j < O) v = W[(size_t)j*2*C + c];
    else {
        int o = j - O;
        v = W[(size_t)o*2*C + C + c] - W[(size_t)o*2*C + c];
    }
    Wcat[t] = v;
}

// ---------------- edge feature max-pool over k ----------------
__global__ void edge_max(const float* __restrict__ Y, const int* __restrict__ idx,
                         const float* __restrict__ gam, const float* __restrict__ bet,
                         float* __restrict__ Fout, int O)
{
    int p = blockIdx.x;          // b*N + n
    int b = p >> 11;
    int o = threadIdx.x;
    __shared__ int sidx[KK];
    if (o < KK) sidx[o] = idx[p*KK + o];
    __syncthreads();

    float s    = gam[o] / sqrtf(1.0f + EPS_BN);
    float bias = bet[o];
    float cc   = Y[(size_t)p*(2*O) + O + o];
    float best = -INFINITY;
    #pragma unroll 5
    for (int k = 0; k < KK; ++k) {
        int m = sidx[k];
        float a = Y[((size_t)(b*NN + m))*(2*O) + o];
        float y = s*(a + cc) + bias;
        y = (y >= 0.f) ? y : SLOPE*y;
        best = fmaxf(best, y);
    }
    Fout[(size_t)p*O + o] = best;
}

// ---------------- out init / decode (ordered-uint atomicMax) -------------
__global__ void init_out(unsigned* o) {
    o[blockIdx.x*256 + threadIdx.x] = 0u;
}
__global__ void decode_out(float* o) {
    int i = blockIdx.x*256 + threadIdx.x;
    unsigned u = ((unsigned*)o)[i];
    o[i] = (u & 0x80000000u) ? __uint_as_float(u & 0x7fffffffu)
                             : __uint_as_float(~u);
}

// ---------------- launch ----------------
extern "C" void kernel_launch(void* const* d_in, const int* in_sizes, int n_in,
                              void* d_out, int out_size)
{
    const float* x = (const float*)d_in[0];
    const float* W[5]; const float* G[5]; const float* Bv[5];

    bool interleaved = (n_in >= 4 && in_sizes[2] == in_sizes[3]);
    if (interleaved) {
        for (int i = 0; i < 5; ++i) {
            W[i]  = (const float*)d_in[1 + 3*i];
            G[i]  = (const float*)d_in[2 + 3*i];
            Bv[i] = (const float*)d_in[3 + 3*i];
        }
    } else {
        for (int i = 0; i < 5; ++i) {
            W[i]  = (const float*)d_in[1 + i];
            G[i]  = (const float*)d_in[6 + i];
            Bv[i] = (const float*)d_in[11 + i];
        }
    }
    float* out = (float*)d_out;

    float *F0,*F1,*F2,*F3,*F4,*negd,*Y,*Wcat,*sq; int* idx;
    cudaGetSymbolAddress((void**)&F0,   g_F0);
    cudaGetSymbolAddress((void**)&F1,   g_F1);
    cudaGetSymbolAddress((void**)&F2,   g_F2);
    cudaGetSymbolAddress((void**)&F3,   g_F3);
    cudaGetSymbolAddress((void**)&F4,   g_F4);
    cudaGetSymbolAddress((void**)&negd, g_negd);
    cudaGetSymbolAddress((void**)&Y,    g_Y);
    cudaGetSymbolAddress((void**)&Wcat, g_Wcat);
    cudaGetSymbolAddress((void**)&sq,   g_sq);
    cudaGetSymbolAddress((void**)&idx,  g_idx);

    transpose_in<<<(BB*3*NN + 255)/256, 256>>>(x, F0);

    struct Layer { const float* Fin; float* Fout; int C; int O; int wi; };
    Layer L[4] = {
        {F0, F1,   3,  64, 0},
        {F1, F2,  64,  64, 1},
        {F2, F3,  64, 128, 2},
        {F3, F4, 128, 256, 3},
    };

    for (int li = 0; li < 4; ++li) {
        int C = L[li].C, O = L[li].O;
        sqnorm_kernel<<<PTS/256, 256>>>(L[li].Fin, sq, C);
        // per-batch: dist GEMM (triangle+mirror) then topk; 16.8MB slice stays in L2
        for (int b = 0; b < BB; ++b) {
            const float* Fb = L[li].Fin + (size_t)b*NN*C;
            gemm128<1><<<dim3(16,16), 256>>>(
                Fb, Fb, negd, NN, C, sq + b*NN, nullptr, nullptr, nullptr);
            topk_radix<<<NN, 256>>>(negd, idx + b*NN*KK);
        }
        prep_wcat<<<(2*O*C + 255)/256, 256>>>(W[L[li].wi], Wcat, O, C);
        gemm128<0><<<dim3(2*O/128, PTS/128), 256>>>(
            L[li].Fin, Wcat, Y, 2*O, C, nullptr, nullptr, nullptr, nullptr);
        edge_max<<<PTS, O>>>(Y, idx, G[L[li].wi], Bv[L[li].wi], L[li].Fout, O);
    }

    // final conv 256 -> 1024 fused with affine+lrelu+max over N
    init_out<<<(BB*1024)/256, 256>>>((unsigned*)out);
    gemm128<2><<<dim3(1024/128, PTS/128), 256>>>(
        F4, W[4], nullptr, 1024, 256, nullptr, G[4], Bv[4], (unsigned*)out);
    decode_out<<<(BB*1024)/256, 256>>>(out);
}

// round 5
// speedup vs baseline: 1.0005x; 1.0005x over previous
#include <cuda_runtime.h>
#include <cuda_bf16.h>
#include <math.h>
#include <stdint.h>

// ---------------- problem constants ----------------
#define BB 4
#define NN 2048
#define KK 20
#define PTS (BB*NN)          // 8192
#define SLOPE 0.2f
#define EPS_BN 1e-5f

// ---------------- device scratch (no allocs allowed) ----------------
__device__ float g_F0[PTS*3];
__device__ float g_F1[PTS*64];
__device__ float g_F2[PTS*64];
__device__ float g_F3[PTS*128];
__device__ float g_F4[PTS*256];
__device__ float g_negd[(size_t)BB*NN*NN];   // 67MB
__device__ int   g_idx[PTS*KK];
__device__ float g_Y[PTS*512];
__device__ float g_Wcat[512*128];
__device__ float g_sq[PTS];

__device__ __forceinline__ unsigned ordkey(float f) {
    unsigned u = __float_as_uint(f);
    return (u & 0x80000000u) ? ~u : (u | 0x80000000u);
}

// ---------------- transpose (B,3,N) -> (B,N,3) ----------------
__global__ void transpose_in(const float* __restrict__ x, float* __restrict__ F0) {
    int t = blockIdx.x*blockDim.x + threadIdx.x;
    if (t >= BB*3*NN) return;
    int b = t / (3*NN);
    int rem = t % (3*NN);
    int c = rem / NN, n = rem % NN;
    F0[(size_t)(b*NN + n)*3 + c] = x[t];
}

// ---------------- squared norms per point ----------------
__global__ void sqnorm_kernel(const float* __restrict__ F, float* __restrict__ sq, int C) {
    int p = blockIdx.x*blockDim.x + threadIdx.x;
    if (p >= PTS) return;
    const float* f = F + (size_t)p*C;
    float s = 0.f;
    for (int c = 0; c < C; ++c) s = fmaf(f[c], f[c], s);
    sq[p] = s;
}

// =====================================================================
// 128x128 tile SGEMM (NT), 256 threads, 8x8 microtile, reg-prefetch.
// MODE 0: Cmat = A Bt^T
// MODE 1: distance epilogue v = 2*acc - sq[i] - sq[j]; triangle grid
//         (bx>=by), mirror store; blockIdx.z = batch.
// MODE 2: fused final layer: affine+lrelu+column-max, atomicMax into outu.
// =====================================================================
template<int MODE>
__global__ __launch_bounds__(256)
void gemm128(const float* __restrict__ A, const float* __restrict__ Bt,
             float* __restrict__ Cmat, int Nc, int K,
             const float* __restrict__ sq,
             const float* __restrict__ gam, const float* __restrict__ bet,
             unsigned* __restrict__ outu)
{
    int bx = blockIdx.x, by = blockIdx.y;
    if (MODE == 1) {
        if (bx < by) return;                 // triangle only
        int bz = blockIdx.z;
        A    += (size_t)bz * NN * K;
        Bt   += (size_t)bz * NN * K;
        Cmat += (size_t)bz * NN * NN;
        sq   += (size_t)bz * NN;
    }

    __shared__ __align__(16) float sbuf[4352];   // As[16][136] + Bs[16][136]
    float* As = sbuf;
    float* Bs = sbuf + 2176;

    int tid = threadIdx.x;
    int tx = tid & 15, ty = tid >> 4;
    int i0 = by * 128, j0 = bx * 128;

    float acc[8][8];
    #pragma unroll
    for (int i = 0; i < 8; ++i)
        #pragma unroll
        for (int j = 0; j < 8; ++j) acc[i][j] = 0.f;

    float ra[8], rb[8];

    auto loadG = [&](int kt) {
        int k0 = kt * 16;
        #pragma unroll
        for (int u = 0; u < 8; ++u) {
            int l = tid + 256*u;
            int r = l >> 4, kk = l & 15;
            bool ok = (k0 + kk) < K;
            ra[u] = ok ? A [(size_t)(i0 + r)*K + k0 + kk] : 0.f;
            rb[u] = ok ? Bt[(size_t)(j0 + r)*K + k0 + kk] : 0.f;
        }
    };
    auto storeS = [&]() {
        #pragma unroll
        for (int u = 0; u < 8; ++u) {
            int l = tid + 256*u;
            int r = l >> 4, kk = l & 15;
            As[kk*136 + r] = ra[u];
            Bs[kk*136 + r] = rb[u];
        }
    };

    int KT = (K + 15) >> 4;
    loadG(0);
    for (int kt = 0; kt < KT; ++kt) {
        __syncthreads();
        storeS();
        __syncthreads();
        if (kt + 1 < KT) loadG(kt + 1);
        #pragma unroll
        for (int k = 0; k < 16; ++k) {
            float4 a0 = *(const float4*)&As[k*136 + ty*8];
            float4 a1 = *(const float4*)&As[k*136 + ty*8 + 4];
            float4 b0 = *(const float4*)&Bs[k*136 + tx*8];
            float4 b1 = *(const float4*)&Bs[k*136 + tx*8 + 4];
            float av[8] = {a0.x,a0.y,a0.z,a0.w,a1.x,a1.y,a1.z,a1.w};
            float bv[8] = {b0.x,b0.y,b0.z,b0.w,b1.x,b1.y,b1.z,b1.w};
            #pragma unroll
            for (int ii = 0; ii < 8; ++ii)
                #pragma unroll
                for (int jj = 0; jj < 8; ++jj)
                    acc[ii][jj] = fmaf(av[ii], bv[jj], acc[ii][jj]);
        }
    }

    if (MODE == 0) {
        #pragma unroll
        for (int ii = 0; ii < 8; ++ii) {
            size_t base = (size_t)(i0 + ty*8 + ii)*Nc + j0 + tx*8;
            *(float4*)&Cmat[base]     = make_float4(acc[ii][0],acc[ii][1],acc[ii][2],acc[ii][3]);
            *(float4*)&Cmat[base + 4] = make_float4(acc[ii][4],acc[ii][5],acc[ii][6],acc[ii][7]);
        }
    }
    else if (MODE == 1) {
        float sqi[8], sqj[8];
        #pragma unroll
        for (int ii = 0; ii < 8; ++ii) sqi[ii] = sq[i0 + ty*8 + ii];
        #pragma unroll
        for (int jj = 0; jj < 8; ++jj) sqj[jj] = sq[j0 + tx*8 + jj];
        #pragma unroll
        for (int ii = 0; ii < 8; ++ii)
            #pragma unroll
            for (int jj = 0; jj < 8; ++jj)
                acc[ii][jj] = 2.0f*acc[ii][jj] - sqi[ii] - sqj[jj];

        #pragma unroll
        for (int ii = 0; ii < 8; ++ii) {
            size_t base = (size_t)(i0 + ty*8 + ii)*Nc + j0 + tx*8;
            *(float4*)&Cmat[base]     = make_float4(acc[ii][0],acc[ii][1],acc[ii][2],acc[ii][3]);
            *(float4*)&Cmat[base + 4] = make_float4(acc[ii][4],acc[ii][5],acc[ii][6],acc[ii][7]);
        }
        if (bx != by) {
            for (int c = 0; c < 4; ++c) {
                __syncthreads();
                if ((tx >> 2) == c) {
                    #pragma unroll
                    for (int jj = 0; jj < 8; ++jj)
                        #pragma unroll
                        for (int ii = 0; ii < 8; ++ii)
                            sbuf[((tx & 3)*8 + jj)*136 + ty*8 + ii] = acc[ii][jj];
                }
                __syncthreads();
                int s2 = tid >> 3;
                int cs = (tid & 7) * 16;
                size_t base = (size_t)(j0 + 32*c + s2)*Nc + i0 + cs;
                #pragma unroll
                for (int w = 0; w < 4; ++w)
                    *(float4*)&Cmat[base + 4*w] =
                        *(const float4*)&sbuf[s2*136 + cs + 4*w];
            }
        }
    }
    else { // MODE == 2
        int b = i0 >> 11;
        float colmax[8];
        #pragma unroll
        for (int jj = 0; jj < 8; ++jj) {
            int col = j0 + tx*8 + jj;
            float sc = gam[col] / sqrtf(1.0f + EPS_BN);
            float bb = bet[col];
            float m = -INFINITY;
            #pragma unroll
            for (int ii = 0; ii < 8; ++ii) {
                float y = fmaf(sc, acc[ii][jj], bb);
                y = (y >= 0.f) ? y : SLOPE*y;
                m = fmaxf(m, y);
            }
            colmax[jj] = m;
        }
        __syncthreads();
        #pragma unroll
        for (int jj = 0; jj < 8; ++jj)
            sbuf[ty*136 + tx*8 + jj] = colmax[jj];
        __syncthreads();
        if (tid < 128) {
            float m = -INFINITY;
            #pragma unroll
            for (int t2 = 0; t2 < 16; ++t2)
                m = fmaxf(m, sbuf[t2*136 + tid]);
            atomicMax(&outu[b*1024 + j0 + tid], ordkey(m));
        }
    }
}

// ---------------- two-level radix top-20 per row ----------------
// Level 1: 11-bit (bits 31:21) histogram finds threshold bin B1.
// Level 2: boundary candidates re-histogrammed on bits 20:10.
// Residue: tiny exact argmax rounds (warp-serial when <=32 cands).
// Tie-break identical to lax.top_k via composite u64 (value desc, idx asc);
// output is the exact top-k SET (order-free: downstream max-pools over k).
__global__ __launch_bounds__(256)
void topk2(const float* __restrict__ negd, int* __restrict__ idx_out)
{
    int row = blockIdx.x;                        // global b*N+n; slice contiguous
    const float* d = negd + (size_t)row * NN;

    __shared__ unsigned hist[2048];
    __shared__ unsigned long long cand[2048];
    __shared__ unsigned warp_suf[8];
    __shared__ int s_B, s_above, s_nout, s_ncand, s_ncand2;
    __shared__ unsigned long long wkey[8];
    __shared__ unsigned long long s_best;

    int t = threadIdx.x;
    unsigned lane = t & 31, wd = t >> 5;

    #pragma unroll
    for (int u = 0; u < 8; ++u) hist[t + 256*u] = 0;
    if (t == 0) { s_nout = 0; s_ncand = 0; s_ncand2 = 0; }
    __syncthreads();

    unsigned ukey[8];
    #pragma unroll
    for (int u = 0; u < 8; ++u) {
        int j = t + 256*u;
        ukey[u] = ordkey(d[j]);
        atomicAdd(&hist[ukey[u] >> 21], 1u);
    }
    __syncthreads();

    // ---- find bin where cumulative (from top) crosses `need` ----
    auto findbin = [&](int need) {
        unsigned local = 0;
        #pragma unroll
        for (int u = 0; u < 8; ++u) local += hist[8*t + u];
        unsigned x = local;
        #pragma unroll
        for (int o = 1; o < 32; o <<= 1) {
            unsigned y = __shfl_down_sync(0xffffffffu, x, o);
            if (lane + o < 32) x += y;
        }
        if (lane == 0) warp_suf[wd] = x;
        __syncthreads();
        unsigned above_warp = 0;
        for (int w = (int)wd + 1; w < 8; ++w) above_warp += warp_suf[w];
        unsigned cum = above_warp + (x - local);
        #pragma unroll
        for (int u = 7; u >= 0; --u) {
            unsigned h = hist[8*t + u];
            if (cum < (unsigned)need && cum + h >= (unsigned)need) {
                s_B = 8*t + u; s_above = (int)cum;
            }
            cum += h;
        }
        __syncthreads();
    };

    findbin(KK);
    int B1 = s_B, above1 = s_above;
    int rem = KK - above1;

    // classify level-1: winners out, boundary -> cand
    #pragma unroll
    for (int u = 0; u < 8; ++u) {
        int j = t + 256*u;
        int bin = ukey[u] >> 21;
        if (bin > B1) {
            int pos = atomicAdd(&s_nout, 1);
            idx_out[row*KK + pos] = j;
        } else if (bin == B1) {
            int pos = atomicAdd(&s_ncand, 1);
            cand[pos] = ((unsigned long long)ukey[u] << 32) | (unsigned)(~j);
        }
    }
    __syncthreads();
    int ncand = s_ncand;

    // ---- level 2: histogram boundary candidates on key bits 20:10 ----
    #pragma unroll
    for (int u = 0; u < 8; ++u) hist[t + 256*u] = 0;
    __syncthreads();
    unsigned long long myc[8]; int mc = 0;
    for (int i = t; i < ncand; i += 256) {
        myc[mc++] = cand[i];
        atomicAdd(&hist[(unsigned)(cand[i] >> 42) & 2047u], 1u);
    }
    __syncthreads();

    findbin(rem);
    int B2 = s_B, above2 = s_above;
    int rem2 = rem - above2;

    for (int m = 0; m < mc; ++m) {
        int bin = (int)((unsigned)(myc[m] >> 42) & 2047u);
        if (bin > B2) {
            int pos = atomicAdd(&s_nout, 1);
            idx_out[row*KK + pos] = (int)(~(unsigned)(myc[m] & 0xffffffffull));
        } else if (bin == B2) {
            int pos = atomicAdd(&s_ncand2, 1);
            cand[pos] = myc[m];   // safe: each thread re-reads only its own regs
        }
    }
    __syncthreads();
    int ncand2 = s_ncand2;
    int base2 = s_nout;

    if (rem2 > 0) {
        if (ncand2 <= 32) {
            // single-warp exact selection
            if (t < 32) {
                unsigned long long k = (t < ncand2) ? cand[t] : 0ull;
                for (int r = 0; r < rem2; ++r) {
                    unsigned long long b = k;
                    #pragma unroll
                    for (int o = 16; o; o >>= 1) {
                        unsigned long long ot = __shfl_xor_sync(0xffffffffu, b, o);
                        b = (ot > b) ? ot : b;
                    }
                    if (k == b) k = 0ull;           // keys unique
                    if (t == 0)
                        idx_out[row*KK + base2 + r] =
                            (int)(~(unsigned)(b & 0xffffffffull));
                }
            }
        } else {
            for (int r = 0; r < rem2; ++r) {
                unsigned long long best = 0ull;
                for (int j = t; j < ncand2; j += 256) {
                    unsigned long long k = cand[j];
                    best = (k > best) ? k : best;
                }
                #pragma unroll
                for (int o = 16; o; o >>= 1) {
                    unsigned long long ot = __shfl_xor_sync(0xffffffffu, best, o);
                    best = (ot > best) ? ot : best;
                }
                if (lane == 0) wkey[wd] = best;
                __syncthreads();
                if (t == 0) {
                    unsigned long long b2 = wkey[0];
                    #pragma unroll
                    for (int w = 1; w < 8; ++w) b2 = (wkey[w] > b2) ? wkey[w] : b2;
                    s_best = b2;
                    idx_out[row*KK + base2 + r] =
                        (int)(~(unsigned)(b2 & 0xffffffffull));
                }
                __syncthreads();
                unsigned long long bb = s_best;
                for (int j = t; j < ncand2; j += 256)
                    if (cand[j] == bb) cand[j] = 0ull;
                __syncthreads();
            }
        }
    }
}

// ---------------- build Wcat = [W_left ; W_right - W_left] ----------------
__global__ void prep_wcat(const float* __restrict__ W, float* __restrict__ Wcat,
                          int O, int C)
{
    int t = blockIdx.x*blockDim.x + threadIdx.x;
    if (t >= 2*O*C) return;
    int j = t / C, c = t % C;
    float v;
    if (j < O) v = W[(size_t)j*2*C + c];
    else {
        int o = j - O;
        v = W[(size_t)o*2*C + C + c] - W[(size_t)o*2*C + c];
    }
    Wcat[t] = v;
}

// ---------------- edge feature max-pool over k ----------------
__global__ void edge_max(const float* __restrict__ Y, const int* __restrict__ idx,
                         const float* __restrict__ gam, const float* __restrict__ bet,
                         float* __restrict__ Fout, int O)
{
    int p = blockIdx.x;
    int b = p >> 11;
    int o = threadIdx.x;
    __shared__ int sidx[KK];
    if (o < KK) sidx[o] = idx[p*KK + o];
    __syncthreads();

    float s    = gam[o] / sqrtf(1.0f + EPS_BN);
    float bias = bet[o];
    float cc   = Y[(size_t)p*(2*O) + O + o];
    float best = -INFINITY;
    #pragma unroll 5
    for (int k = 0; k < KK; ++k) {
        int m = sidx[k];
        float a = Y[((size_t)(b*NN + m))*(2*O) + o];
        float y = s*(a + cc) + bias;
        y = (y >= 0.f) ? y : SLOPE*y;
        best = fmaxf(best, y);
    }
    Fout[(size_t)p*O + o] = best;
}

// ---------------- out init / decode (ordered-uint atomicMax) -------------
__global__ void init_out(unsigned* o) {
    o[blockIdx.x*256 + threadIdx.x] = 0u;
}
__global__ void decode_out(float* o) {
    int i = blockIdx.x*256 + threadIdx.x;
    unsigned u = ((unsigned*)o)[i];
    o[i] = (u & 0x80000000u) ? __uint_as_float(u & 0x7fffffffu)
                             : __uint_as_float(~u);
}

// ---------------- launch ----------------
extern "C" void kernel_launch(void* const* d_in, const int* in_sizes, int n_in,
                              void* d_out, int out_size)
{
    const float* x = (const float*)d_in[0];
    const float* W[5]; const float* G[5]; const float* Bv[5];

    bool interleaved = (n_in >= 4 && in_sizes[2] == in_sizes[3]);
    if (interleaved) {
        for (int i = 0; i < 5; ++i) {
            W[i]  = (const float*)d_in[1 + 3*i];
            G[i]  = (const float*)d_in[2 + 3*i];
            Bv[i] = (const float*)d_in[3 + 3*i];
        }
    } else {
        for (int i = 0; i < 5; ++i) {
            W[i]  = (const float*)d_in[1 + i];
            G[i]  = (const float*)d_in[6 + i];
            Bv[i] = (const float*)d_in[11 + i];
        }
    }
    float* out = (float*)d_out;

    float *F0,*F1,*F2,*F3,*F4,*negd,*Y,*Wcat,*sq; int* idx;
    cudaGetSymbolAddress((void**)&F0,   g_F0);
    cudaGetSymbolAddress((void**)&F1,   g_F1);
    cudaGetSymbolAddress((void**)&F2,   g_F2);
    cudaGetSymbolAddress((void**)&F3,   g_F3);
    cudaGetSymbolAddress((void**)&F4,   g_F4);
    cudaGetSymbolAddress((void**)&negd, g_negd);
    cudaGetSymbolAddress((void**)&Y,    g_Y);
    cudaGetSymbolAddress((void**)&Wcat, g_Wcat);
    cudaGetSymbolAddress((void**)&sq,   g_sq);
    cudaGetSymbolAddress((void**)&idx,  g_idx);

    transpose_in<<<(BB*3*NN + 255)/256, 256>>>(x, F0);

    struct Layer { const float* Fin; float* Fout; int C; int O; int wi; };
    Layer L[4] = {
        {F0, F1,   3,  64, 0},
        {F1, F2,  64,  64, 1},
        {F2, F3,  64, 128, 2},
        {F3, F4, 128, 256, 3},
    };

    for (int li = 0; li < 4; ++li) {
        int C = L[li].C, O = L[li].O;
        sqnorm_kernel<<<PTS/256, 256>>>(L[li].Fin, sq, C);
        gemm128<1><<<dim3(16,16,BB), 256>>>(
            L[li].Fin, L[li].Fin, negd, NN, C, sq, nullptr, nullptr, nullptr);
        topk2<<<PTS, 256>>>(negd, idx);
        prep_wcat<<<(2*O*C + 255)/256, 256>>>(W[L[li].wi], Wcat, O, C);
        gemm128<0><<<dim3(2*O/128, PTS/128), 256>>>(
            L[li].Fin, Wcat, Y, 2*O, C, nullptr, nullptr, nullptr, nullptr);
        edge_max<<<PTS, O>>>(Y, idx, G[L[li].wi], Bv[L[li].wi], L[li].Fout, O);
    }

    init_out<<<(BB*1024)/256, 256>>>((unsigned*)out);
    gemm128<2><<<dim3(1024/128, PTS/128), 256>>>(
        F4, W[4], nullptr, 1024, 256, nullptr, G[4], Bv[4], (unsigned*)out);
    decode_out<<<(BB*1024)/256, 256>>>(out);
}

// round 6
// speedup vs baseline: 1.1193x; 1.1187x over previous
#include <cuda_runtime.h>
#include <cuda_bf16.h>
#include <math.h>
#include <stdint.h>

// ---------------- problem constants ----------------
#define BB 4
#define NN 2048
#define KK 20
#define PTS (BB*NN)          // 8192
#define SLOPE 0.2f
#define EPS_BN 1e-5f

// ---------------- device scratch (no allocs allowed) ----------------
__device__ float g_F0[PTS*3];
__device__ float g_F1[PTS*64];
__device__ float g_F2[PTS*64];
__device__ float g_F3[PTS*128];
__device__ float g_F4[PTS*256];
__device__ float g_negd[(size_t)BB*NN*NN];   // 67MB
__device__ int   g_idx[PTS*KK];
__device__ float g_Y[PTS*512];
__device__ float g_Wcat[512*128];
__device__ float g_sq[PTS];

__device__ __forceinline__ unsigned ordkey(float f) {
    unsigned u = __float_as_uint(f);
    return (u & 0x80000000u) ? ~u : (u | 0x80000000u);
}

// ---------------- transpose (B,3,N) -> (B,N,3) ----------------
__global__ void transpose_in(const float* __restrict__ x, float* __restrict__ F0) {
    int t = blockIdx.x*blockDim.x + threadIdx.x;
    if (t >= BB*3*NN) return;
    int b = t / (3*NN);
    int rem = t % (3*NN);
    int c = rem / NN, n = rem % NN;
    F0[(size_t)(b*NN + n)*3 + c] = x[t];
}

// ---------------- squared norms per point ----------------
__global__ void sqnorm_kernel(const float* __restrict__ F, float* __restrict__ sq, int C) {
    int p = blockIdx.x*blockDim.x + threadIdx.x;
    if (p >= PTS) return;
    const float* f = F + (size_t)p*C;
    float s = 0.f;
    for (int c = 0; c < C; ++c) s = fmaf(f[c], f[c], s);
    sq[p] = s;
}

// =====================================================================
// 128x128 tile SGEMM (NT), 256 threads, 8x8 microtile, reg-prefetch.
// MODE 0: Cmat = A Bt^T
// MODE 1: distance epilogue v = 2*acc - sq[i] - sq[j]; triangle grid
//         (bx>=by), mirror store; blockIdx.z = batch.
// MODE 2: fused final layer: affine+lrelu+column-max, atomicMax into outu.
// =====================================================================
template<int MODE>
__global__ __launch_bounds__(256)
void gemm128(const float* __restrict__ A, const float* __restrict__ Bt,
             float* __restrict__ Cmat, int Nc, int K,
             const float* __restrict__ sq,
             const float* __restrict__ gam, const float* __restrict__ bet,
             unsigned* __restrict__ outu)
{
    int bx = blockIdx.x, by = blockIdx.y;
    if (MODE == 1) {
        if (bx < by) return;                 // triangle only
        int bz = blockIdx.z;
        A    += (size_t)bz * NN * K;
        Bt   += (size_t)bz * NN * K;
        Cmat += (size_t)bz * NN * NN;
        sq   += (size_t)bz * NN;
    }

    __shared__ __align__(16) float sbuf[4352];   // As[16][136] + Bs[16][136]
    float* As = sbuf;
    float* Bs = sbuf + 2176;

    int tid = threadIdx.x;
    int tx = tid & 15, ty = tid >> 4;
    int i0 = by * 128, j0 = bx * 128;

    float acc[8][8];
    #pragma unroll
    for (int i = 0; i < 8; ++i)
        #pragma unroll
        for (int j = 0; j < 8; ++j) acc[i][j] = 0.f;

    float ra[8], rb[8];

    auto loadG = [&](int kt) {
        int k0 = kt * 16;
        #pragma unroll
        for (int u = 0; u < 8; ++u) {
            int l = tid + 256*u;
            int r = l >> 4, kk = l & 15;
            bool ok = (k0 + kk) < K;
            ra[u] = ok ? A [(size_t)(i0 + r)*K + k0 + kk] : 0.f;
            rb[u] = ok ? Bt[(size_t)(j0 + r)*K + k0 + kk] : 0.f;
        }
    };
    auto storeS = [&]() {
        #pragma unroll
        for (int u = 0; u < 8; ++u) {
            int l = tid + 256*u;
            int r = l >> 4, kk = l & 15;
            As[kk*136 + r] = ra[u];
            Bs[kk*136 + r] = rb[u];
        }
    };

    int KT = (K + 15) >> 4;
    loadG(0);
    for (int kt = 0; kt < KT; ++kt) {
        __syncthreads();
        storeS();
        __syncthreads();
        if (kt + 1 < KT) loadG(kt + 1);
        #pragma unroll
        for (int k = 0; k < 16; ++k) {
            float4 a0 = *(const float4*)&As[k*136 + ty*8];
            float4 a1 = *(const float4*)&As[k*136 + ty*8 + 4];
            float4 b0 = *(const float4*)&Bs[k*136 + tx*8];
            float4 b1 = *(const float4*)&Bs[k*136 + tx*8 + 4];
            float av[8] = {a0.x,a0.y,a0.z,a0.w,a1.x,a1.y,a1.z,a1.w};
            float bv[8] = {b0.x,b0.y,b0.z,b0.w,b1.x,b1.y,b1.z,b1.w};
            #pragma unroll
            for (int ii = 0; ii < 8; ++ii)
                #pragma unroll
                for (int jj = 0; jj < 8; ++jj)
                    acc[ii][jj] = fmaf(av[ii], bv[jj], acc[ii][jj]);
        }
    }

    if (MODE == 0) {
        #pragma unroll
        for (int ii = 0; ii < 8; ++ii) {
            size_t base = (size_t)(i0 + ty*8 + ii)*Nc + j0 + tx*8;
            *(float4*)&Cmat[base]     = make_float4(acc[ii][0],acc[ii][1],acc[ii][2],acc[ii][3]);
            *(float4*)&Cmat[base + 4] = make_float4(acc[ii][4],acc[ii][5],acc[ii][6],acc[ii][7]);
        }
    }
    else if (MODE == 1) {
        float sqi[8], sqj[8];
        #pragma unroll
        for (int ii = 0; ii < 8; ++ii) sqi[ii] = sq[i0 + ty*8 + ii];
        #pragma unroll
        for (int jj = 0; jj < 8; ++jj) sqj[jj] = sq[j0 + tx*8 + jj];
        #pragma unroll
        for (int ii = 0; ii < 8; ++ii)
            #pragma unroll
            for (int jj = 0; jj < 8; ++jj)
                acc[ii][jj] = 2.0f*acc[ii][jj] - sqi[ii] - sqj[jj];

        #pragma unroll
        for (int ii = 0; ii < 8; ++ii) {
            size_t base = (size_t)(i0 + ty*8 + ii)*Nc + j0 + tx*8;
            *(float4*)&Cmat[base]     = make_float4(acc[ii][0],acc[ii][1],acc[ii][2],acc[ii][3]);
            *(float4*)&Cmat[base + 4] = make_float4(acc[ii][4],acc[ii][5],acc[ii][6],acc[ii][7]);
        }
        if (bx != by) {
            for (int c = 0; c < 4; ++c) {
                __syncthreads();
                if ((tx >> 2) == c) {
                    #pragma unroll
                    for (int jj = 0; jj < 8; ++jj)
                        #pragma unroll
                        for (int ii = 0; ii < 8; ++ii)
                            sbuf[((tx & 3)*8 + jj)*136 + ty*8 + ii] = acc[ii][jj];
                }
                __syncthreads();
                int s2 = tid >> 3;
                int cs = (tid & 7) * 16;
                size_t base = (size_t)(j0 + 32*c + s2)*Nc + i0 + cs;
                #pragma unroll
                for (int w = 0; w < 4; ++w)
                    *(float4*)&Cmat[base + 4*w] =
                        *(const float4*)&sbuf[s2*136 + cs + 4*w];
            }
        }
    }
    else { // MODE == 2
        int b = i0 >> 11;
        float colmax[8];
        #pragma unroll
        for (int jj = 0; jj < 8; ++jj) {
            int col = j0 + tx*8 + jj;
            float sc = gam[col] / sqrtf(1.0f + EPS_BN);
            float bb = bet[col];
            float m = -INFINITY;
            #pragma unroll
            for (int ii = 0; ii < 8; ++ii) {
                float y = fmaf(sc, acc[ii][jj], bb);
                y = (y >= 0.f) ? y : SLOPE*y;
                m = fmaxf(m, y);
            }
            colmax[jj] = m;
        }
        __syncthreads();
        #pragma unroll
        for (int jj = 0; jj < 8; ++jj)
            sbuf[ty*136 + tx*8 + jj] = colmax[jj];
        __syncthreads();
        if (tid < 128) {
            float m = -INFINITY;
            #pragma unroll
            for (int t2 = 0; t2 < 16; ++t2)
                m = fmaxf(m, sbuf[t2*136 + tid]);
            atomicMax(&outu[b*1024 + j0 + tid], ordkey(m));
        }
    }
}

// ---------------- linear-bin top-20 per row ----------------
// Row min/max -> 2048 uniform value bins (near-zero atomic contention,
// boundary bin ~1-3 elems). Winners by bin; boundary resolved exactly with
// u64 (value,index) keys matching lax.top_k tie-break. Output = exact
// top-k SET (order-free: downstream max-pools over k).
__global__ __launch_bounds__(256)
void topk_lin(const float* __restrict__ negd, int* __restrict__ idx_out)
{
    int row = blockIdx.x;
    const float* d = negd + (size_t)row * NN;

    __shared__ unsigned hist[2048];
    __shared__ unsigned long long cand[2048];
    __shared__ unsigned warp_suf[8];
    __shared__ float red[16];
    __shared__ int s_B, s_above, s_nout, s_ncand;
    __shared__ unsigned long long wkey[8];
    __shared__ unsigned long long s_best;

    int t = threadIdx.x;
    unsigned lane = t & 31, wd = t >> 5;

    #pragma unroll
    for (int u = 0; u < 8; ++u) hist[t + 256*u] = 0;
    if (t == 0) { s_nout = 0; s_ncand = 0; }

    // load 8 values via 2 float4 (coalesced); element j = u*1024 + 4*t + i
    float v[8];
    {
        float4 a = *(const float4*)&d[4*t];
        float4 b = *(const float4*)&d[1024 + 4*t];
        v[0]=a.x; v[1]=a.y; v[2]=a.z; v[3]=a.w;
        v[4]=b.x; v[5]=b.y; v[6]=b.z; v[7]=b.w;
    }

    // block min/max
    float mn = v[0], mx = v[0];
    #pragma unroll
    for (int u = 1; u < 8; ++u) { mn = fminf(mn, v[u]); mx = fmaxf(mx, v[u]); }
    #pragma unroll
    for (int o = 16; o; o >>= 1) {
        mn = fminf(mn, __shfl_xor_sync(0xffffffffu, mn, o));
        mx = fmaxf(mx, __shfl_xor_sync(0xffffffffu, mx, o));
    }
    if (lane == 0) { red[wd] = mn; red[8 + wd] = mx; }
    __syncthreads();
    mn = red[0]; mx = red[8];
    #pragma unroll
    for (int w = 1; w < 8; ++w) {
        mn = fminf(mn, red[w]); mx = fmaxf(mx, red[8 + w]);
    }
    float scale = (mx > mn) ? 2047.0f / (mx - mn) : 0.0f;

    // histogram into uniform bins
    int bin[8];
    #pragma unroll
    for (int u = 0; u < 8; ++u) {
        int bi = (int)((v[u] - mn) * scale);
        bi = bi < 0 ? 0 : (bi > 2047 ? 2047 : bi);
        bin[u] = bi;
        atomicAdd(&hist[bi], 1u);
    }
    __syncthreads();

    // suffix-scan to find threshold bin B with cum-from-top crossing KK
    unsigned local = 0;
    #pragma unroll
    for (int u = 0; u < 8; ++u) local += hist[8*t + u];
    unsigned x = local;
    #pragma unroll
    for (int o = 1; o < 32; o <<= 1) {
        unsigned y = __shfl_down_sync(0xffffffffu, x, o);
        if (lane + o < 32) x += y;
    }
    if (lane == 0) warp_suf[wd] = x;
    __syncthreads();
    unsigned above_warp = 0;
    for (int w = (int)wd + 1; w < 8; ++w) above_warp += warp_suf[w];
    unsigned cum = above_warp + (x - local);
    #pragma unroll
    for (int u = 7; u >= 0; --u) {
        unsigned h = hist[8*t + u];
        if (cum < (unsigned)KK && cum + h >= (unsigned)KK) {
            s_B = 8*t + u; s_above = (int)cum;
        }
        cum += h;
    }
    __syncthreads();
    int B = s_B;
    int rem = KK - s_above;

    // classify
    #pragma unroll
    for (int u = 0; u < 8; ++u) {
        int j = (u & 4 ? 1024 : 0) + 4*t + (u & 3);
        if (bin[u] > B) {
            int pos = atomicAdd(&s_nout, 1);
            idx_out[row*KK + pos] = j;
        } else if (bin[u] == B) {
            int pos = atomicAdd(&s_ncand, 1);
            cand[pos] = ((unsigned long long)ordkey(v[u]) << 32) | (unsigned)(~j);
        }
    }
    __syncthreads();
    int ncand = s_ncand;
    int base = s_nout;

    if (rem > 0) {
        if (ncand <= 32) {
            if (t < 32) {
                unsigned long long k = (t < (unsigned)ncand) ? cand[t] : 0ull;
                for (int r = 0; r < rem; ++r) {
                    unsigned long long b = k;
                    #pragma unroll
                    for (int o = 16; o; o >>= 1) {
                        unsigned long long ot = __shfl_xor_sync(0xffffffffu, b, o);
                        b = (ot > b) ? ot : b;
                    }
                    if (k == b) k = 0ull;           // keys unique
                    if (t == 0)
                        idx_out[row*KK + base + r] =
                            (int)(~(unsigned)(b & 0xffffffffull));
                }
            }
        } else {
            for (int r = 0; r < rem; ++r) {
                unsigned long long best = 0ull;
                for (int j = t; j < ncand; j += 256) {
                    unsigned long long k = cand[j];
                    best = (k > best) ? k : best;
                }
                #pragma unroll
                for (int o = 16; o; o >>= 1) {
                    unsigned long long ot = __shfl_xor_sync(0xffffffffu, best, o);
                    best = (ot > best) ? ot : best;
                }
                if (lane == 0) wkey[wd] = best;
                __syncthreads();
                if (t == 0) {
                    unsigned long long b2 = wkey[0];
                    #pragma unroll
                    for (int w = 1; w < 8; ++w) b2 = (wkey[w] > b2) ? wkey[w] : b2;
                    s_best = b2;
                    idx_out[row*KK + base + r] =
                        (int)(~(unsigned)(b2 & 0xffffffffull));
                }
                __syncthreads();
                unsigned long long bb = s_best;
                for (int j = t; j < ncand; j += 256)
                    if (cand[j] == bb) cand[j] = 0ull;
                __syncthreads();
            }
        }
    }
}

// ---------------- build Wcat = [W_left ; W_right - W_left] ----------------
__global__ void prep_wcat(const float* __restrict__ W, float* __restrict__ Wcat,
                          int O, int C)
{
    int t = blockIdx.x*blockDim.x + threadIdx.x;
    if (t >= 2*O*C) return;
    int j = t / C, c = t % C;
    float v;
    if (j < O) v = W[(size_t)j*2*C + c];
    else {
        int o = j - O;
        v = W[(size_t)o*2*C + C + c] - W[(size_t)o*2*C + c];
    }
    Wcat[t] = v;
}

// ---------------- edge feature max-pool over k ----------------
__global__ void edge_max(const float* __restrict__ Y, const int* __restrict__ idx,
                         const float* __restrict__ gam, const float* __restrict__ bet,
                         float* __restrict__ Fout, int O)
{
    int p = blockIdx.x;
    int b = p >> 11;
    int o = threadIdx.x;
    __shared__ int sidx[KK];
    if (o < KK) sidx[o] = idx[p*KK + o];
    __syncthreads();

    float s    = gam[o] / sqrtf(1.0f + EPS_BN);
    float bias = bet[o];
    float cc   = Y[(size_t)p*(2*O) + O + o];
    float best = -INFINITY;
    #pragma unroll 5
    for (int k = 0; k < KK; ++k) {
        int m = sidx[k];
        float a = Y[((size_t)(b*NN + m))*(2*O) + o];
        float y = s*(a + cc) + bias;
        y = (y >= 0.f) ? y : SLOPE*y;
        best = fmaxf(best, y);
    }
    Fout[(size_t)p*O + o] = best;
}

// ---------------- out init / decode (ordered-uint atomicMax) -------------
__global__ void init_out(unsigned* o) {
    o[blockIdx.x*256 + threadIdx.x] = 0u;
}
__global__ void decode_out(float* o) {
    int i = blockIdx.x*256 + threadIdx.x;
    unsigned u = ((unsigned*)o)[i];
    o[i] = (u & 0x80000000u) ? __uint_as_float(u & 0x7fffffffu)
                             : __uint_as_float(~u);
}

// ---------------- launch ----------------
extern "C" void kernel_launch(void* const* d_in, const int* in_sizes, int n_in,
                              void* d_out, int out_size)
{
    const float* x = (const float*)d_in[0];
    const float* W[5]; const float* G[5]; const float* Bv[5];

    bool interleaved = (n_in >= 4 && in_sizes[2] == in_sizes[3]);
    if (interleaved) {
        for (int i = 0; i < 5; ++i) {
            W[i]  = (const float*)d_in[1 + 3*i];
            G[i]  = (const float*)d_in[2 + 3*i];
            Bv[i] = (const float*)d_in[3 + 3*i];
        }
    } else {
        for (int i = 0; i < 5; ++i) {
            W[i]  = (const float*)d_in[1 + i];
            G[i]  = (const float*)d_in[6 + i];
            Bv[i] = (const float*)d_in[11 + i];
        }
    }
    float* out = (float*)d_out;

    float *F0,*F1,*F2,*F3,*F4,*negd,*Y,*Wcat,*sq; int* idx;
    cudaGetSymbolAddress((void**)&F0,   g_F0);
    cudaGetSymbolAddress((void**)&F1,   g_F1);
    cudaGetSymbolAddress((void**)&F2,   g_F2);
    cudaGetSymbolAddress((void**)&F3,   g_F3);
    cudaGetSymbolAddress((void**)&F4,   g_F4);
    cudaGetSymbolAddress((void**)&negd, g_negd);
    cudaGetSymbolAddress((void**)&Y,    g_Y);
    cudaGetSymbolAddress((void**)&Wcat, g_Wcat);
    cudaGetSymbolAddress((void**)&sq,   g_sq);
    cudaGetSymbolAddress((void**)&idx,  g_idx);

    transpose_in<<<(BB*3*NN + 255)/256, 256>>>(x, F0);

    struct Layer { const float* Fin; float* Fout; int C; int O; int wi; };
    Layer L[4] = {
        {F0, F1,   3,  64, 0},
        {F1, F2,  64,  64, 1},
        {F2, F3,  64, 128, 2},
        {F3, F4, 128, 256, 3},
    };

    for (int li = 0; li < 4; ++li) {
        int C = L[li].C, O = L[li].O;
        sqnorm_kernel<<<PTS/256, 256>>>(L[li].Fin, sq, C);
        gemm128<1><<<dim3(16,16,BB), 256>>>(
            L[li].Fin, L[li].Fin, negd, NN, C, sq, nullptr, nullptr, nullptr);
        topk_lin<<<PTS, 256>>>(negd, idx);
        prep_wcat<<<(2*O*C + 255)/256, 256>>>(W[L[li].wi], Wcat, O, C);
        gemm128<0><<<dim3(2*O/128, PTS/128), 256>>>(
            L[li].Fin, Wcat, Y, 2*O, C, nullptr, nullptr, nullptr, nullptr);
        edge_max<<<PTS, O>>>(Y, idx, G[L[li].wi], Bv[L[li].wi], L[li].Fout, O);
    }

    init_out<<<(BB*1024)/256, 256>>>((unsigned*)out);
    gemm128<2><<<dim3(1024/128, PTS/128), 256>>>(
        F4, W[4], nullptr, 1024, 256, nullptr, G[4], Bv[4], (unsigned*)out);
    decode_out<<<(BB*1024)/256, 256>>>(out);
}

// round 7
// speedup vs baseline: 1.2251x; 1.0945x over previous
#include <cuda_runtime.h>
#include <cuda_bf16.h>
#include <math.h>
#include <stdint.h>

// ---------------- problem constants ----------------
#define BB 4
#define NN 2048
#define KK 20
#define PTS (BB*NN)          // 8192
#define SLOPE 0.2f
#define EPS_BN 1e-5f
#define NBIN 256
#define CANDCAP 256

// ---------------- device scratch (no allocs allowed) ----------------
__device__ float g_F0[PTS*3];
__device__ float g_F1[PTS*64];
__device__ float g_F2[PTS*64];
__device__ float g_F3[PTS*128];
__device__ float g_F4[PTS*256];
__device__ float g_negd[(size_t)BB*NN*NN];   // 67MB
__device__ int   g_idx[PTS*KK];
__device__ float g_Y[PTS*512];
__device__ float g_Wcat[512*128];
__device__ float g_sq[PTS];

__device__ __forceinline__ unsigned ordkey(float f) {
    unsigned u = __float_as_uint(f);
    return (u & 0x80000000u) ? ~u : (u | 0x80000000u);
}

// ---------------- transpose (B,3,N) -> (B,N,3) ----------------
__global__ void transpose_in(const float* __restrict__ x, float* __restrict__ F0) {
    int t = blockIdx.x*blockDim.x + threadIdx.x;
    if (t >= BB*3*NN) return;
    int b = t / (3*NN);
    int rem = t % (3*NN);
    int c = rem / NN, n = rem % NN;
    F0[(size_t)(b*NN + n)*3 + c] = x[t];
}

// ---------------- squared norms per point ----------------
__global__ void sqnorm_kernel(const float* __restrict__ F, float* __restrict__ sq, int C) {
    int p = blockIdx.x*blockDim.x + threadIdx.x;
    if (p >= PTS) return;
    const float* f = F + (size_t)p*C;
    float s = 0.f;
    for (int c = 0; c < C; ++c) s = fmaf(f[c], f[c], s);
    sq[p] = s;
}

// =====================================================================
// 128x128 tile SGEMM (NT), 256 threads, 8x8 microtile, reg-prefetch.
// MODE 0: Cmat = A Bt^T
// MODE 1: distance epilogue v = 2*acc - sq[i] - sq[j]; triangle grid
//         (bx>=by), mirror store; blockIdx.z = batch.
// MODE 2: fused final layer: affine+lrelu+column-max, atomicMax into outu.
// =====================================================================
template<int MODE>
__global__ __launch_bounds__(256)
void gemm128(const float* __restrict__ A, const float* __restrict__ Bt,
             float* __restrict__ Cmat, int Nc, int K,
             const float* __restrict__ sq,
             const float* __restrict__ gam, const float* __restrict__ bet,
             unsigned* __restrict__ outu)
{
    int bx = blockIdx.x, by = blockIdx.y;
    if (MODE == 1) {
        if (bx < by) return;                 // triangle only
        int bz = blockIdx.z;
        A    += (size_t)bz * NN * K;
        Bt   += (size_t)bz * NN * K;
        Cmat += (size_t)bz * NN * NN;
        sq   += (size_t)bz * NN;
    }

    __shared__ __align__(16) float sbuf[4352];   // As[16][136] + Bs[16][136]
    float* As = sbuf;
    float* Bs = sbuf + 2176;

    int tid = threadIdx.x;
    int tx = tid & 15, ty = tid >> 4;
    int i0 = by * 128, j0 = bx * 128;

    float acc[8][8];
    #pragma unroll
    for (int i = 0; i < 8; ++i)
        #pragma unroll
        for (int j = 0; j < 8; ++j) acc[i][j] = 0.f;

    float ra[8], rb[8];

    auto loadG = [&](int kt) {
        int k0 = kt * 16;
        #pragma unroll
        for (int u = 0; u < 8; ++u) {
            int l = tid + 256*u;
            int r = l >> 4, kk = l & 15;
            bool ok = (k0 + kk) < K;
            ra[u] = ok ? A [(size_t)(i0 + r)*K + k0 + kk] : 0.f;
            rb[u] = ok ? Bt[(size_t)(j0 + r)*K + k0 + kk] : 0.f;
        }
    };
    auto storeS = [&]() {
        #pragma unroll
        for (int u = 0; u < 8; ++u) {
            int l = tid + 256*u;
            int r = l >> 4, kk = l & 15;
            As[kk*136 + r] = ra[u];
            Bs[kk*136 + r] = rb[u];
        }
    };

    int KT = (K + 15) >> 4;
    loadG(0);
    for (int kt = 0; kt < KT; ++kt) {
        __syncthreads();
        storeS();
        __syncthreads();
        if (kt + 1 < KT) loadG(kt + 1);
        #pragma unroll
        for (int k = 0; k < 16; ++k) {
            float4 a0 = *(const float4*)&As[k*136 + ty*8];
            float4 a1 = *(const float4*)&As[k*136 + ty*8 + 4];
            float4 b0 = *(const float4*)&Bs[k*136 + tx*8];
            float4 b1 = *(const float4*)&Bs[k*136 + tx*8 + 4];
            float av[8] = {a0.x,a0.y,a0.z,a0.w,a1.x,a1.y,a1.z,a1.w};
            float bv[8] = {b0.x,b0.y,b0.z,b0.w,b1.x,b1.y,b1.z,b1.w};
            #pragma unroll
            for (int ii = 0; ii < 8; ++ii)
                #pragma unroll
                for (int jj = 0; jj < 8; ++jj)
                    acc[ii][jj] = fmaf(av[ii], bv[jj], acc[ii][jj]);
        }
    }

    if (MODE == 0) {
        #pragma unroll
        for (int ii = 0; ii < 8; ++ii) {
            size_t base = (size_t)(i0 + ty*8 + ii)*Nc + j0 + tx*8;
            *(float4*)&Cmat[base]     = make_float4(acc[ii][0],acc[ii][1],acc[ii][2],acc[ii][3]);
            *(float4*)&Cmat[base + 4] = make_float4(acc[ii][4],acc[ii][5],acc[ii][6],acc[ii][7]);
        }
    }
    else if (MODE == 1) {
        float sqi[8], sqj[8];
        #pragma unroll
        for (int ii = 0; ii < 8; ++ii) sqi[ii] = sq[i0 + ty*8 + ii];
        #pragma unroll
        for (int jj = 0; jj < 8; ++jj) sqj[jj] = sq[j0 + tx*8 + jj];
        #pragma unroll
        for (int ii = 0; ii < 8; ++ii)
            #pragma unroll
            for (int jj = 0; jj < 8; ++jj)
                acc[ii][jj] = 2.0f*acc[ii][jj] - sqi[ii] - sqj[jj];

        #pragma unroll
        for (int ii = 0; ii < 8; ++ii) {
            size_t base = (size_t)(i0 + ty*8 + ii)*Nc + j0 + tx*8;
            *(float4*)&Cmat[base]     = make_float4(acc[ii][0],acc[ii][1],acc[ii][2],acc[ii][3]);
            *(float4*)&Cmat[base + 4] = make_float4(acc[ii][4],acc[ii][5],acc[ii][6],acc[ii][7]);
        }
        if (bx != by) {
            for (int c = 0; c < 4; ++c) {
                __syncthreads();
                if ((tx >> 2) == c) {
                    #pragma unroll
                    for (int jj = 0; jj < 8; ++jj)
                        #pragma unroll
                        for (int ii = 0; ii < 8; ++ii)
                            sbuf[((tx & 3)*8 + jj)*136 + ty*8 + ii] = acc[ii][jj];
                }
                __syncthreads();
                int s2 = tid >> 3;
                int cs = (tid & 7) * 16;
                size_t base = (size_t)(j0 + 32*c + s2)*Nc + i0 + cs;
                #pragma unroll
                for (int w = 0; w < 4; ++w)
                    *(float4*)&Cmat[base + 4*w] =
                        *(const float4*)&sbuf[s2*136 + cs + 4*w];
            }
        }
    }
    else { // MODE == 2
        int b = i0 >> 11;
        float colmax[8];
        #pragma unroll
        for (int jj = 0; jj < 8; ++jj) {
            int col = j0 + tx*8 + jj;
            float sc = gam[col] / sqrtf(1.0f + EPS_BN);
            float bb = bet[col];
            float m = -INFINITY;
            #pragma unroll
            for (int ii = 0; ii < 8; ++ii) {
                float y = fmaf(sc, acc[ii][jj], bb);
                y = (y >= 0.f) ? y : SLOPE*y;
                m = fmaxf(m, y);
            }
            colmax[jj] = m;
        }
        __syncthreads();
        #pragma unroll
        for (int jj = 0; jj < 8; ++jj)
            sbuf[ty*136 + tx*8 + jj] = colmax[jj];
        __syncthreads();
        if (tid < 128) {
            float m = -INFINITY;
            #pragma unroll
            for (int t2 = 0; t2 < 16; ++t2)
                m = fmaxf(m, sbuf[t2*136 + tid]);
            atomicMax(&outu[b*1024 + j0 + tid], ordkey(m));
        }
    }
}

// ---------------- linear-bin top-20 per row (256 bins, small smem) -------
// Row min/max -> 256 uniform value bins. Winners by bin; boundary resolved
// exactly with u64 (value,index) keys (lax.top_k tie-break). Candidate
// buffer capped; guarded writes + exact register-resident fallback keep it
// correct for any distribution. Output = exact top-k SET.
__global__ __launch_bounds__(256)
void topk_lin(const float* __restrict__ negd, int* __restrict__ idx_out)
{
    int row = blockIdx.x;
    const float* d = negd + (size_t)row * NN;

    __shared__ unsigned hist[NBIN];
    __shared__ unsigned long long cand[CANDCAP];
    __shared__ unsigned warp_suf[8];
    __shared__ float red[16];
    __shared__ int s_B, s_above, s_nout, s_ncand;
    __shared__ unsigned long long wkey[8];
    __shared__ unsigned long long s_best;

    int t = threadIdx.x;
    unsigned lane = t & 31, wd = t >> 5;

    if (t < NBIN) hist[t] = 0;
    if (t == 0) { s_nout = 0; s_ncand = 0; }

    // 8 values via 2 float4; element j = (u<4 ? 0 : 1024) + 4*t + (u&3)
    float v[8];
    {
        float4 a = *(const float4*)&d[4*t];
        float4 b = *(const float4*)&d[1024 + 4*t];
        v[0]=a.x; v[1]=a.y; v[2]=a.z; v[3]=a.w;
        v[4]=b.x; v[5]=b.y; v[6]=b.z; v[7]=b.w;
    }

    // block min/max
    float mn = v[0], mx = v[0];
    #pragma unroll
    for (int u = 1; u < 8; ++u) { mn = fminf(mn, v[u]); mx = fmaxf(mx, v[u]); }
    #pragma unroll
    for (int o = 16; o; o >>= 1) {
        mn = fminf(mn, __shfl_xor_sync(0xffffffffu, mn, o));
        mx = fmaxf(mx, __shfl_xor_sync(0xffffffffu, mx, o));
    }
    if (lane == 0) { red[wd] = mn; red[8 + wd] = mx; }
    __syncthreads();
    mn = red[0]; mx = red[8];
    #pragma unroll
    for (int w = 1; w < 8; ++w) {
        mn = fminf(mn, red[w]); mx = fmaxf(mx, red[8 + w]);
    }
    float scale = (mx > mn) ? (float)(NBIN - 1) / (mx - mn) : 0.0f;

    int bin[8];
    #pragma unroll
    for (int u = 0; u < 8; ++u) {
        int bi = (int)((v[u] - mn) * scale);
        bi = bi < 0 ? 0 : (bi > NBIN-1 ? NBIN-1 : bi);
        bin[u] = bi;
        atomicAdd(&hist[bi], 1u);
    }
    __syncthreads();

    // suffix scan: thread t owns bin t (t < NBIN)
    unsigned local = (t < NBIN) ? hist[t] : 0;
    unsigned x = local;
    #pragma unroll
    for (int o = 1; o < 32; o <<= 1) {
        unsigned y = __shfl_down_sync(0xffffffffu, x, o);
        if (lane + o < 32) x += y;
    }
    if (lane == 0) warp_suf[wd] = x;
    __syncthreads();
    if (t < NBIN) {
        unsigned above_warp = 0;
        for (int w = (int)wd + 1; w < NBIN/32; ++w) above_warp += warp_suf[w];
        unsigned cum = above_warp + (x - local);     // strictly above bin t
        if (cum < (unsigned)KK && cum + local >= (unsigned)KK) {
            s_B = t; s_above = (int)cum;
        }
    }
    __syncthreads();
    int B = s_B;
    int rem = KK - s_above;

    // classify: winners out; boundary -> cand (guarded)
    #pragma unroll
    for (int u = 0; u < 8; ++u) {
        int j = (u & 4 ? 1024 : 0) + 4*t + (u & 3);
        if (bin[u] > B) {
            int pos = atomicAdd(&s_nout, 1);
            idx_out[row*KK + pos] = j;
        } else if (bin[u] == B) {
            int pos = atomicAdd(&s_ncand, 1);
            if (pos < CANDCAP)
                cand[pos] = ((unsigned long long)ordkey(v[u]) << 32) | (unsigned)(~j);
        }
    }
    __syncthreads();
    int ncand = s_ncand;
    int base = s_nout;

    if (rem <= 0) return;

    if (ncand <= 32) {
        if (t < 32) {
            unsigned long long k = (t < ncand) ? cand[t] : 0ull;
            for (int r = 0; r < rem; ++r) {
                unsigned long long b = k;
                #pragma unroll
                for (int o = 16; o; o >>= 1) {
                    unsigned long long ot = __shfl_xor_sync(0xffffffffu, b, o);
                    b = (ot > b) ? ot : b;
                }
                if (k == b) k = 0ull;           // keys unique
                if (t == 0)
                    idx_out[row*KK + base + r] =
                        (int)(~(unsigned)(b & 0xffffffffull));
            }
        }
    } else if (ncand <= CANDCAP) {
        for (int r = 0; r < rem; ++r) {
            unsigned long long best = 0ull;
            for (int j = t; j < ncand; j += 256) {
                unsigned long long k = cand[j];
                best = (k > best) ? k : best;
            }
            #pragma unroll
            for (int o = 16; o; o >>= 1) {
                unsigned long long ot = __shfl_xor_sync(0xffffffffu, best, o);
                best = (ot > best) ? ot : best;
            }
            if (lane == 0) wkey[wd] = best;
            __syncthreads();
            if (t == 0) {
                unsigned long long b2 = wkey[0];
                #pragma unroll
                for (int w = 1; w < 8; ++w) b2 = (wkey[w] > b2) ? wkey[w] : b2;
                s_best = b2;
                idx_out[row*KK + base + r] =
                    (int)(~(unsigned)(b2 & 0xffffffffull));
            }
            __syncthreads();
            unsigned long long bb = s_best;
            for (int j = t; j < ncand; j += 256)
                if (cand[j] == bb) cand[j] = 0ull;
            __syncthreads();
        }
    } else {
        // overflow fallback: exact argmax rounds from register-resident keys
        unsigned long long kloc[8];
        #pragma unroll
        for (int u = 0; u < 8; ++u) {
            int j = (u & 4 ? 1024 : 0) + 4*t + (u & 3);
            kloc[u] = (bin[u] == B)
                ? (((unsigned long long)ordkey(v[u]) << 32) | (unsigned)(~j))
                : 0ull;
        }
        for (int r = 0; r < rem; ++r) {
            unsigned long long best = 0ull;
            #pragma unroll
            for (int u = 0; u < 8; ++u)
                best = (kloc[u] > best) ? kloc[u] : best;
            #pragma unroll
            for (int o = 16; o; o >>= 1) {
                unsigned long long ot = __shfl_xor_sync(0xffffffffu, best, o);
                best = (ot > best) ? ot : best;
            }
            if (lane == 0) wkey[wd] = best;
            __syncthreads();
            if (t == 0) {
                unsigned long long b2 = wkey[0];
                #pragma unroll
                for (int w = 1; w < 8; ++w) b2 = (wkey[w] > b2) ? wkey[w] : b2;
                s_best = b2;
                idx_out[row*KK + base + r] =
                    (int)(~(unsigned)(b2 & 0xffffffffull));
            }
            __syncthreads();
            unsigned long long bb = s_best;
            #pragma unroll
            for (int u = 0; u < 8; ++u)
                if (kloc[u] == bb) kloc[u] = 0ull;
            __syncthreads();
        }
    }
}

// ---------------- build Wcat = gamma/sqrt(1+eps) * [W_l ; W_r - W_l] -----
__global__ void prep_wcat(const float* __restrict__ W, const float* __restrict__ gam,
                          float* __restrict__ Wcat, int O, int C)
{
    int t = blockIdx.x*blockDim.x + threadIdx.x;
    if (t >= 2*O*C) return;
    int j = t / C, c = t % C;
    int o = (j < O) ? j : j - O;
    float s = gam[o] / sqrtf(1.0f + EPS_BN);
    float v;
    if (j < O) v = W[(size_t)j*2*C + c];
    else       v = W[(size_t)o*2*C + C + c] - W[(size_t)o*2*C + c];
    Wcat[t] = s * v;
}

// ---------------- edge feature max-pool over k (scale pre-folded) --------
__global__ void edge_max(const float* __restrict__ Y, const int* __restrict__ idx,
                         const float* __restrict__ bet,
                         float* __restrict__ Fout, int O)
{
    int p = blockIdx.x;
    int b = p >> 11;
    int o = threadIdx.x;
    __shared__ int sidx[KK];
    if (o < KK) sidx[o] = idx[p*KK + o];
    __syncthreads();

    float ccb = Y[(size_t)p*(2*O) + O + o] + bet[o];
    float best = -INFINITY;
    #pragma unroll 5
    for (int k = 0; k < KK; ++k) {
        int m = sidx[k];
        float y = Y[((size_t)(b*NN + m))*(2*O) + o] + ccb;
        y = (y >= 0.f) ? y : SLOPE*y;
        best = fmaxf(best, y);
    }
    Fout[(size_t)p*O + o] = best;
}

// ---------------- out init / decode (ordered-uint atomicMax) -------------
__global__ void init_out(unsigned* o) {
    o[blockIdx.x*256 + threadIdx.x] = 0u;
}
__global__ void decode_out(float* o) {
    int i = blockIdx.x*256 + threadIdx.x;
    unsigned u = ((unsigned*)o)[i];
    o[i] = (u & 0x80000000u) ? __uint_as_float(u & 0x7fffffffu)
                             : __uint_as_float(~u);
}

// ---------------- launch ----------------
extern "C" void kernel_launch(void* const* d_in, const int* in_sizes, int n_in,
                              void* d_out, int out_size)
{
    const float* x = (const float*)d_in[0];
    const float* W[5]; const float* G[5]; const float* Bv[5];

    bool interleaved = (n_in >= 4 && in_sizes[2] == in_sizes[3]);
    if (interleaved) {
        for (int i = 0; i < 5; ++i) {
            W[i]  = (const float*)d_in[1 + 3*i];
            G[i]  = (const float*)d_in[2 + 3*i];
            Bv[i] = (const float*)d_in[3 + 3*i];
        }
    } else {
        for (int i = 0; i < 5; ++i) {
            W[i]  = (const float*)d_in[1 + i];
            G[i]  = (const float*)d_in[6 + i];
            Bv[i] = (const float*)d_in[11 + i];
        }
    }
    float* out = (float*)d_out;

    float *F0,*F1,*F2,*F3,*F4,*negd,*Y,*Wcat,*sq; int* idx;
    cudaGetSymbolAddress((void**)&F0,   g_F0);
    cudaGetSymbolAddress((void**)&F1,   g_F1);
    cudaGetSymbolAddress((void**)&F2,   g_F2);
    cudaGetSymbolAddress((void**)&F3,   g_F3);
    cudaGetSymbolAddress((void**)&F4,   g_F4);
    cudaGetSymbolAddress((void**)&negd, g_negd);
    cudaGetSymbolAddress((void**)&Y,    g_Y);
    cudaGetSymbolAddress((void**)&Wcat, g_Wcat);
    cudaGetSymbolAddress((void**)&sq,   g_sq);
    cudaGetSymbolAddress((void**)&idx,  g_idx);

    transpose_in<<<(BB*3*NN + 255)/256, 256>>>(x, F0);

    struct Layer { const float* Fin; float* Fout; int C; int O; int wi; };
    Layer L[4] = {
        {F0, F1,   3,  64, 0},
        {F1, F2,  64,  64, 1},
        {F2, F3,  64, 128, 2},
        {F3, F4, 128, 256, 3},
    };

    for (int li = 0; li < 4; ++li) {
        int C = L[li].C, O = L[li].O;
        sqnorm_kernel<<<PTS/256, 256>>>(L[li].Fin, sq, C);
        gemm128<1><<<dim3(16,16,BB), 256>>>(
            L[li].Fin, L[li].Fin, negd, NN, C, sq, nullptr, nullptr, nullptr);
        topk_lin<<<PTS, 256>>>(negd, idx);
        prep_wcat<<<(2*O*C + 255)/256, 256>>>(W[L[li].wi], G[L[li].wi], Wcat, O, C);
        gemm128<0><<<dim3(2*O/128, PTS/128), 256>>>(
            L[li].Fin, Wcat, Y, 2*O, C, nullptr, nullptr, nullptr, nullptr);
        edge_max<<<PTS, O>>>(Y, idx, Bv[L[li].wi], L[li].Fout, O);
    }

    init_out<<<(BB*1024)/256, 256>>>((unsigned*)out);
    gemm128<2><<<dim3(1024/128, PTS/128), 256>>>(
        F4, W[4], nullptr, 1024, 256, nullptr, G[4], Bv[4], (unsigned*)out);
    decode_out<<<(BB*1024)/256, 256>>>(out);
}

// round 9
// speedup vs baseline: 1.2474x; 1.0182x over previous
#include <cuda_runtime.h>
#include <cuda_bf16.h>
#include <mma.h>
#include <math.h>
#include <stdint.h>

using namespace nvcuda;

// ---------------- problem constants ----------------
#define BB 4
#define NN 2048
#define KK 20
#define PTS (BB*NN)          // 8192
#define SLOPE 0.2f
#define EPS_BN 1e-5f
#define NBIN 256
#define CANDCAP 256

// ---------------- device scratch (no allocs allowed) ----------------
__device__ float g_F0[PTS*3];
__device__ float g_F1[PTS*64];
__device__ float g_F2[PTS*64];
__device__ float g_F3[PTS*128];
__device__ float g_F4[PTS*256];
__device__ float g_negd[(size_t)BB*NN*NN];   // 67MB
__device__ int   g_idx[PTS*KK];
__device__ float g_Y[PTS*512];
__device__ float g_Wcat[1024*256];           // fp32 weight staging (max final)
__device__ float g_sq[PTS];
__device__ __nv_bfloat16 g_Fa[(size_t)PTS*768];   // split A operand
__device__ __nv_bfloat16 g_Wb[(size_t)1024*768];  // split B operand

__device__ __forceinline__ unsigned ordkey(float f) {
    unsigned u = __float_as_uint(f);
    return (u & 0x80000000u) ? ~u : (u | 0x80000000u);
}

// ---------------- transpose (B,3,N) -> (B,N,3) ----------------
__global__ void transpose_in(const float* __restrict__ x, float* __restrict__ F0) {
    int t = blockIdx.x*blockDim.x + threadIdx.x;
    if (t >= BB*3*NN) return;
    int b = t / (3*NN);
    int rem = t % (3*NN);
    int c = rem / NN, n = rem % NN;
    F0[(size_t)(b*NN + n)*3 + c] = x[t];
}

// ---------------- squared norms per point ----------------
__global__ void sqnorm_kernel(const float* __restrict__ F, float* __restrict__ sq, int C) {
    int p = blockIdx.x*blockDim.x + threadIdx.x;
    if (p >= PTS) return;
    const float* f = F + (size_t)p*C;
    float s = 0.f;
    for (int c = 0; c < C; ++c) s = fmaf(f[c], f[c], s);
    sq[p] = s;
}

// ============ fp32 distance GEMM (exact kNN), 128x128 tile ============
__global__ __launch_bounds__(256)
void gemm_dist(const float* __restrict__ A, float* __restrict__ Cmat, int K,
               const float* __restrict__ sq)
{
    int bx = blockIdx.x, by = blockIdx.y;
    if (bx < by) return;                 // triangle only
    int bz = blockIdx.z;
    A    += (size_t)bz * NN * K;
    Cmat += (size_t)bz * NN * NN;
    sq   += (size_t)bz * NN;

    __shared__ __align__(16) float sbuf[4352];
    float* As = sbuf;
    float* Bs = sbuf + 2176;

    int tid = threadIdx.x;
    int tx = tid & 15, ty = tid >> 4;
    int i0 = by * 128, j0 = bx * 128;

    float acc[8][8];
    #pragma unroll
    for (int i = 0; i < 8; ++i)
        #pragma unroll
        for (int j = 0; j < 8; ++j) acc[i][j] = 0.f;

    float ra[8], rb[8];
    auto loadG = [&](int kt) {
        int k0 = kt * 16;
        #pragma unroll
        for (int u = 0; u < 8; ++u) {
            int l = tid + 256*u;
            int r = l >> 4, kk = l & 15;
            bool ok = (k0 + kk) < K;
            ra[u] = ok ? A[(size_t)(i0 + r)*K + k0 + kk] : 0.f;
            rb[u] = ok ? A[(size_t)(j0 + r)*K + k0 + kk] : 0.f;
        }
    };
    auto storeS = [&]() {
        #pragma unroll
        for (int u = 0; u < 8; ++u) {
            int l = tid + 256*u;
            int r = l >> 4, kk = l & 15;
            As[kk*136 + r] = ra[u];
            Bs[kk*136 + r] = rb[u];
        }
    };

    int KT = (K + 15) >> 4;
    loadG(0);
    for (int kt = 0; kt < KT; ++kt) {
        __syncthreads();
        storeS();
        __syncthreads();
        if (kt + 1 < KT) loadG(kt + 1);
        #pragma unroll
        for (int k = 0; k < 16; ++k) {
            float4 a0 = *(const float4*)&As[k*136 + ty*8];
            float4 a1 = *(const float4*)&As[k*136 + ty*8 + 4];
            float4 b0 = *(const float4*)&Bs[k*136 + tx*8];
            float4 b1 = *(const float4*)&Bs[k*136 + tx*8 + 4];
            float av[8] = {a0.x,a0.y,a0.z,a0.w,a1.x,a1.y,a1.z,a1.w};
            float bv[8] = {b0.x,b0.y,b0.z,b0.w,b1.x,b1.y,b1.z,b1.w};
            #pragma unroll
            for (int ii = 0; ii < 8; ++ii)
                #pragma unroll
                for (int jj = 0; jj < 8; ++jj)
                    acc[ii][jj] = fmaf(av[ii], bv[jj], acc[ii][jj]);
        }
    }

    float sqi[8], sqj[8];
    #pragma unroll
    for (int ii = 0; ii < 8; ++ii) sqi[ii] = sq[i0 + ty*8 + ii];
    #pragma unroll
    for (int jj = 0; jj < 8; ++jj) sqj[jj] = sq[j0 + tx*8 + jj];
    #pragma unroll
    for (int ii = 0; ii < 8; ++ii)
        #pragma unroll
        for (int jj = 0; jj < 8; ++jj)
            acc[ii][jj] = 2.0f*acc[ii][jj] - sqi[ii] - sqj[jj];

    #pragma unroll
    for (int ii = 0; ii < 8; ++ii) {
        size_t base = (size_t)(i0 + ty*8 + ii)*NN + j0 + tx*8;
        *(float4*)&Cmat[base]     = make_float4(acc[ii][0],acc[ii][1],acc[ii][2],acc[ii][3]);
        *(float4*)&Cmat[base + 4] = make_float4(acc[ii][4],acc[ii][5],acc[ii][6],acc[ii][7]);
    }
    if (bx != by) {
        for (int c = 0; c < 4; ++c) {
            __syncthreads();
            if ((tx >> 2) == c) {
                #pragma unroll
                for (int jj = 0; jj < 8; ++jj)
                    #pragma unroll
                    for (int ii = 0; ii < 8; ++ii)
                        sbuf[((tx & 3)*8 + jj)*136 + ty*8 + ii] = acc[ii][jj];
            }
            __syncthreads();
            int s2 = tid >> 3;
            int cs = (tid & 7) * 16;
            size_t base = (size_t)(j0 + 32*c + s2)*NN + i0 + cs;
            #pragma unroll
            for (int w = 0; w < 4; ++w)
                *(float4*)&Cmat[base + 4*w] =
                    *(const float4*)&sbuf[s2*136 + cs + 4*w];
        }
    }
}

// ============ wmma bf16-split GEMM (NT), 128x128 tile, 8 warps ==========
// MODE 0: write fp32 Y tile.  MODE 1: col-max + bet + lrelu + atomicMax.
// Warp grid 4(m) x 2(n): each warp 32x64 via 2x4 m16n16k16 frags.
template<int MODE>
__global__ __launch_bounds__(256)
void gemm_wmma(const __nv_bfloat16* __restrict__ Ab, const __nv_bfloat16* __restrict__ Bb,
               int Wpad, int Nc, float* __restrict__ Yout,
               const float* __restrict__ bet, unsigned* __restrict__ outu)
{
    extern __shared__ __align__(16) char smem[];
    __nv_bfloat16* sA = (__nv_bfloat16*)smem;            // 128 x 24
    __nv_bfloat16* sB = (__nv_bfloat16*)(smem + 6144);   // 128 x 24

    int tid = threadIdx.x;
    int wid = tid >> 5;
    int wm = wid & 3, wn = wid >> 2;
    int i0 = blockIdx.y*128, j0 = blockIdx.x*128;

    wmma::fragment<wmma::accumulator,16,16,16,float> acc[2][4];
    #pragma unroll
    for (int i = 0; i < 2; ++i)
        #pragma unroll
        for (int j = 0; j < 4; ++j) wmma::fill_fragment(acc[i][j], 0.0f);

    int r = tid >> 1, c8 = (tid & 1)*8;
    for (int k0 = 0; k0 < Wpad; k0 += 16) {
        *(uint4*)&sA[r*24 + c8] = *(const uint4*)&Ab[(size_t)(i0+r)*Wpad + k0 + c8];
        *(uint4*)&sB[r*24 + c8] = *(const uint4*)&Bb[(size_t)(j0+r)*Wpad + k0 + c8];
        __syncthreads();
        wmma::fragment<wmma::matrix_a,16,16,16,__nv_bfloat16,wmma::row_major> af[2];
        wmma::fragment<wmma::matrix_b,16,16,16,__nv_bfloat16,wmma::col_major> bf[4];
        #pragma unroll
        for (int i = 0; i < 2; ++i)
            wmma::load_matrix_sync(af[i], &sA[(wm*32 + i*16)*24], 24);
        #pragma unroll
        for (int j = 0; j < 4; ++j)
            wmma::load_matrix_sync(bf[j], &sB[(wn*64 + j*16)*24], 24);
        #pragma unroll
        for (int i = 0; i < 2; ++i)
            #pragma unroll
            for (int j = 0; j < 4; ++j)
                wmma::mma_sync(acc[i][j], af[i], bf[j], acc[i][j]);
        __syncthreads();
    }

    if (MODE == 0) {
        #pragma unroll
        for (int i = 0; i < 2; ++i)
            #pragma unroll
            for (int j = 0; j < 4; ++j)
                wmma::store_matrix_sync(
                    &Yout[(size_t)(i0 + wm*32 + i*16)*Nc + j0 + wn*64 + j*16],
                    acc[i][j], Nc, wmma::mem_row_major);
    } else {
        // per-warp 32x68 fp32 stage, then column max across all 128 rows
        float* epi = (float*)smem;   // 8 * 32 * 68 floats = 69632 B
        #pragma unroll
        for (int i = 0; i < 2; ++i)
            #pragma unroll
            for (int j = 0; j < 4; ++j)
                wmma::store_matrix_sync(&epi[wid*2176 + (i*16)*68 + j*16],
                                        acc[i][j], 68, wmma::mem_row_major);
        __syncthreads();
        if (tid < 128) {
            int col = tid;
            int wnc = col >> 6, cl = col & 63;
            float m = -INFINITY;
            #pragma unroll
            for (int wmc = 0; wmc < 4; ++wmc) {
                const float* p = &epi[(wnc*4 + wmc)*2176 + cl];
                #pragma unroll 8
                for (int rr = 0; rr < 32; ++rr)
                    m = fmaxf(m, p[rr*68]);
            }
            float y = m + bet[j0 + col];
            y = (y >= 0.f) ? y : SLOPE*y;
            atomicMax(&outu[(i0 >> 11)*1024 + j0 + col], ordkey(y));
        }
    }
}

// ---------------- bf16 split: pat=0 -> [hi,lo,hi], pat=1 -> [hi,hi,lo] ----
__global__ void split_mat(const float* __restrict__ S, __nv_bfloat16* __restrict__ D,
                          int rows, int C, int Wpad, int patB)
{
    int t = blockIdx.x*256 + threadIdx.x;
    if (t >= rows*Wpad) return;
    int r = t / Wpad, k = t - r*Wpad;
    float out = 0.f;
    if (k < 3*C) {
        int blk = k / C, c = k - blk*C;
        int lo = patB ? (blk == 2) : (blk == 1);
        float x = S[(size_t)r*C + c];
        __nv_bfloat16 h = __float2bfloat16(x);
        out = lo ? (x - __bfloat162float(h)) : x;
    }
    D[(size_t)r*Wpad + k] = __float2bfloat16(out);
}

// ---------------- linear-bin top-20 per row (256 bins) -------------------
__global__ __launch_bounds__(256)
void topk_lin(const float* __restrict__ negd, int* __restrict__ idx_out)
{
    int row = blockIdx.x;
    const float* d = negd + (size_t)row * NN;

    __shared__ unsigned hist[NBIN];
    __shared__ unsigned long long cand[CANDCAP];
    __shared__ unsigned warp_suf[8];
    __shared__ float red[16];
    __shared__ int s_B, s_above, s_nout, s_ncand;
    __shared__ unsigned long long wkey[8];
    __shared__ unsigned long long s_best;

    int t = threadIdx.x;
    unsigned lane = t & 31, wd = t >> 5;

    if (t < NBIN) hist[t] = 0;
    if (t == 0) { s_nout = 0; s_ncand = 0; }

    float v[8];
    {
        float4 a = *(const float4*)&d[4*t];
        float4 b = *(const float4*)&d[1024 + 4*t];
        v[0]=a.x; v[1]=a.y; v[2]=a.z; v[3]=a.w;
        v[4]=b.x; v[5]=b.y; v[6]=b.z; v[7]=b.w;
    }

    float mn = v[0], mx = v[0];
    #pragma unroll
    for (int u = 1; u < 8; ++u) { mn = fminf(mn, v[u]); mx = fmaxf(mx, v[u]); }
    #pragma unroll
    for (int o = 16; o; o >>= 1) {
        mn = fminf(mn, __shfl_xor_sync(0xffffffffu, mn, o));
        mx = fmaxf(mx, __shfl_xor_sync(0xffffffffu, mx, o));
    }
    if (lane == 0) { red[wd] = mn; red[8 + wd] = mx; }
    __syncthreads();
    mn = red[0]; mx = red[8];
    #pragma unroll
    for (int w = 1; w < 8; ++w) {
        mn = fminf(mn, red[w]); mx = fmaxf(mx, red[8 + w]);
    }
    float scale = (mx > mn) ? (float)(NBIN - 1) / (mx - mn) : 0.0f;

    int bin[8];
    #pragma unroll
    for (int u = 0; u < 8; ++u) {
        int bi = (int)((v[u] - mn) * scale);
        bi = bi < 0 ? 0 : (bi > NBIN-1 ? NBIN-1 : bi);
        bin[u] = bi;
        atomicAdd(&hist[bi], 1u);
    }
    __syncthreads();

    unsigned local = (t < NBIN) ? hist[t] : 0;
    unsigned x = local;
    #pragma unroll
    for (int o = 1; o < 32; o <<= 1) {
        unsigned y = __shfl_down_sync(0xffffffffu, x, o);
        if (lane + o < 32) x += y;
    }
    if (lane == 0) warp_suf[wd] = x;
    __syncthreads();
    if (t < NBIN) {
        unsigned above_warp = 0;
        for (int w = (int)wd + 1; w < NBIN/32; ++w) above_warp += warp_suf[w];
        unsigned cum = above_warp + (x - local);
        if (cum < (unsigned)KK && cum + local >= (unsigned)KK) {
            s_B = t; s_above = (int)cum;
        }
    }
    __syncthreads();
    int B = s_B;
    int rem = KK - s_above;

    #pragma unroll
    for (int u = 0; u < 8; ++u) {
        int j = (u & 4 ? 1024 : 0) + 4*t + (u & 3);
        if (bin[u] > B) {
            int pos = atomicAdd(&s_nout, 1);
            idx_out[row*KK + pos] = j;
        } else if (bin[u] == B) {
            int pos = atomicAdd(&s_ncand, 1);
            if (pos < CANDCAP)
                cand[pos] = ((unsigned long long)ordkey(v[u]) << 32) | (unsigned)(~j);
        }
    }
    __syncthreads();
    int ncand = s_ncand;
    int base = s_nout;

    if (rem <= 0) return;

    if (ncand <= 32) {
        if (t < 32) {
            unsigned long long k = (t < ncand) ? cand[t] : 0ull;
            for (int r = 0; r < rem; ++r) {
                unsigned long long b = k;
                #pragma unroll
                for (int o = 16; o; o >>= 1) {
                    unsigned long long ot = __shfl_xor_sync(0xffffffffu, b, o);
                    b = (ot > b) ? ot : b;
                }
                if (k == b) k = 0ull;
                if (t == 0)
                    idx_out[row*KK + base + r] = (int)(~(unsigned)(b & 0xffffffffull));
            }
        }
    } else if (ncand <= CANDCAP) {
        for (int r = 0; r < rem; ++r) {
            unsigned long long best = 0ull;
            for (int j = t; j < ncand; j += 256) {
                unsigned long long k = cand[j];
                best = (k > best) ? k : best;
            }
            #pragma unroll
            for (int o = 16; o; o >>= 1) {
                unsigned long long ot = __shfl_xor_sync(0xffffffffu, best, o);
                best = (ot > best) ? ot : best;
            }
            if (lane == 0) wkey[wd] = best;
            __syncthreads();
            if (t == 0) {
                unsigned long long b2 = wkey[0];
                #pragma unroll
                for (int w = 1; w < 8; ++w) b2 = (wkey[w] > b2) ? wkey[w] : b2;
                s_best = b2;
                idx_out[row*KK + base + r] = (int)(~(unsigned)(b2 & 0xffffffffull));
            }
            __syncthreads();
            unsigned long long bb = s_best;
            for (int j = t; j < ncand; j += 256)
                if (cand[j] == bb) cand[j] = 0ull;
            __syncthreads();
        }
    } else {
        unsigned long long kloc[8];
        #pragma unroll
        for (int u = 0; u < 8; ++u) {
            int j = (u & 4 ? 1024 : 0) + 4*t + (u & 3);
            kloc[u] = (bin[u] == B)
                ? (((unsigned long long)ordkey(v[u]) << 32) | (unsigned)(~j))
                : 0ull;
        }
        for (int r = 0; r < rem; ++r) {
            unsigned long long best = 0ull;
            #pragma unroll
            for (int u = 0; u < 8; ++u)
                best = (kloc[u] > best) ? kloc[u] : best;
            #pragma unroll
            for (int o = 16; o; o >>= 1) {
                unsigned long long ot = __shfl_xor_sync(0xffffffffu, best, o);
                best = (ot > best) ? ot : best;
            }
            if (lane == 0) wkey[wd] = best;
            __syncthreads();
            if (t == 0) {
                unsigned long long b2 = wkey[0];
                #pragma unroll
                for (int w = 1; w < 8; ++w) b2 = (wkey[w] > b2) ? wkey[w] : b2;
                s_best = b2;
                idx_out[row*KK + base + r] = (int)(~(unsigned)(b2 & 0xffffffffull));
            }
            __syncthreads();
            unsigned long long bb = s_best;
            #pragma unroll
            for (int u = 0; u < 8; ++u)
                if (kloc[u] == bb) kloc[u] = 0ull;
            __syncthreads();
        }
    }
}

// ---------------- build Wcat = gamma/sqrt(1+eps) * [W_l ; W_r - W_l] -----
__global__ void prep_wcat(const float* __restrict__ W, const float* __restrict__ gam,
                          float* __restrict__ Wcat, int O, int C)
{
    int t = blockIdx.x*blockDim.x + threadIdx.x;
    if (t >= 2*O*C) return;
    int j = t / C, c = t % C;
    int o = (j < O) ? j : j - O;
    float s = gam[o] / sqrtf(1.0f + EPS_BN);
    float v;
    if (j < O) v = W[(size_t)j*2*C + c];
    else       v = W[(size_t)o*2*C + C + c] - W[(size_t)o*2*C + c];
    Wcat[t] = s * v;
}

// ---------------- final weight: W5s = gamma/sqrt(1+eps) * W5 -------------
__global__ void prep_w5(const float* __restrict__ W, const float* __restrict__ gam,
                        float* __restrict__ Ws)
{
    int t = blockIdx.x*blockDim.x + threadIdx.x;
    if (t >= 1024*256) return;
    int o = t >> 8;
    Ws[t] = (gam[o] / sqrtf(1.0f + EPS_BN)) * W[t];
}

// ---------------- edge feature max-pool over k (max-first, lrelu once) ----
__global__ void edge_max(const float* __restrict__ Y, const int* __restrict__ idx,
                         const float* __restrict__ bet,
                         float* __restrict__ Fout, int O)
{
    int p = blockIdx.x;
    int b = p >> 11;
    int o = threadIdx.x;
    __shared__ int sidx[KK];
    if (o < KK) sidx[o] = idx[p*KK + o];
    __syncthreads();

    float best = -INFINITY;
    #pragma unroll 5
    for (int k = 0; k < KK; ++k) {
        int m = sidx[k];
        best = fmaxf(best, Y[((size_t)(b*NN + m))*(2*O) + o]);
    }
    float y = best + Y[(size_t)p*(2*O) + O + o] + bet[o];
    y = (y >= 0.f) ? y : SLOPE*y;
    Fout[(size_t)p*O + o] = y;
}

// ---------------- out init / decode (ordered-uint atomicMax) -------------
__global__ void init_out(unsigned* o) {
    o[blockIdx.x*256 + threadIdx.x] = 0u;
}
__global__ void decode_out(float* o) {
    int i = blockIdx.x*256 + threadIdx.x;
    unsigned u = ((unsigned*)o)[i];
    o[i] = (u & 0x80000000u) ? __uint_as_float(u & 0x7fffffffu)
                             : __uint_as_float(~u);
}

// ---------------- launch ----------------
extern "C" void kernel_launch(void* const* d_in, const int* in_sizes, int n_in,
                              void* d_out, int out_size)
{
    const float* x = (const float*)d_in[0];
    const float* W[5]; const float* G[5]; const float* Bv[5];

    bool interleaved = (n_in >= 4 && in_sizes[2] == in_sizes[3]);
    if (interleaved) {
        for (int i = 0; i < 5; ++i) {
            W[i]  = (const float*)d_in[1 + 3*i];
            G[i]  = (const float*)d_in[2 + 3*i];
            Bv[i] = (const float*)d_in[3 + 3*i];
        }
    } else {
        for (int i = 0; i < 5; ++i) {
            W[i]  = (const float*)d_in[1 + i];
            G[i]  = (const float*)d_in[6 + i];
            Bv[i] = (const float*)d_in[11 + i];
        }
    }
    float* out = (float*)d_out;

    float *F0,*F1,*F2,*F3,*F4,*negd,*Y,*Wcat,*sq; int* idx;
    __nv_bfloat16 *Fa, *Wb;
    cudaGetSymbolAddress((void**)&F0,   g_F0);
    cudaGetSymbolAddress((void**)&F1,   g_F1);
    cudaGetSymbolAddress((void**)&F2,   g_F2);
    cudaGetSymbolAddress((void**)&F3,   g_F3);
    cudaGetSymbolAddress((void**)&F4,   g_F4);
    cudaGetSymbolAddress((void**)&negd, g_negd);
    cudaGetSymbolAddress((void**)&Y,    g_Y);
    cudaGetSymbolAddress((void**)&Wcat, g_Wcat);
    cudaGetSymbolAddress((void**)&sq,   g_sq);
    cudaGetSymbolAddress((void**)&idx,  g_idx);
    cudaGetSymbolAddress((void**)&Fa,   g_Fa);
    cudaGetSymbolAddress((void**)&Wb,   g_Wb);

    const int SMEM_Y   = 12288;   // sA + sB
    const int SMEM_FIN = 69632;   // epilogue stage (reuses mainloop space)
    cudaFuncSetAttribute(gemm_wmma<1>, cudaFuncAttributeMaxDynamicSharedMemorySize, SMEM_FIN);

    transpose_in<<<(BB*3*NN + 255)/256, 256>>>(x, F0);

    struct Layer { const float* Fin; float* Fout; int C; int O; int wi; };
    Layer L[4] = {
        {F0, F1,   3,  64, 0},
        {F1, F2,  64,  64, 1},
        {F2, F3,  64, 128, 2},
        {F3, F4, 128, 256, 3},
    };

    for (int li = 0; li < 4; ++li) {
        int C = L[li].C, O = L[li].O;
        int Wpad = ((3*C + 15)/16)*16;
        sqnorm_kernel<<<PTS/256, 256>>>(L[li].Fin, sq, C);
        gemm_dist<<<dim3(16,16,BB), 256>>>(L[li].Fin, negd, C, sq);
        topk_lin<<<PTS, 256>>>(negd, idx);
        prep_wcat<<<(2*O*C + 255)/256, 256>>>(W[L[li].wi], G[L[li].wi], Wcat, O, C);
        split_mat<<<(PTS*Wpad + 255)/256, 256>>>(L[li].Fin, Fa, PTS, C, Wpad, 0);
        split_mat<<<(2*O*Wpad + 255)/256, 256>>>(Wcat, Wb, 2*O, C, Wpad, 1);
        gemm_wmma<0><<<dim3(2*O/128, PTS/128), 256, SMEM_Y>>>(
            Fa, Wb, Wpad, 2*O, Y, nullptr, nullptr);
        edge_max<<<PTS, O>>>(Y, idx, Bv[L[li].wi], L[li].Fout, O);
    }

    // final conv 256 -> 1024 fused with +bias, lrelu, max over N
    prep_w5<<<(1024*256 + 255)/256, 256>>>(W[4], G[4], Wcat);
    split_mat<<<(PTS*768 + 255)/256, 256>>>(F4, Fa, PTS, 256, 768, 0);
    split_mat<<<(1024*768 + 255)/256, 256>>>(Wcat, Wb, 1024, 768/3, 768, 1);
    init_out<<<(BB*1024)/256, 256>>>((unsigned*)out);
    gemm_wmma<1><<<dim3(8, PTS/128), 256, SMEM_FIN>>>(
        Fa, Wb, 768, 0, nullptr, Bv[4], (unsigned*)out);
    decode_out<<<(BB*1024)/256, 256>>>(out);
}